// round 10
// baseline (speedup 1.0000x reference)
#include <cuda_runtime.h>
#include <cuda_fp16.h>
#include <cstdint>

#define Bn 8
#define Sn 1024
#define En 1024
#define Hn 16
#define Dn 64
#define ATTN_ELEMS ((size_t)Bn*Hn*Sn*Sn)
#define IN_ELEMS (Bn*Sn*En)     // 8388608
#define W_ELEMS  (En*En)        // 1048576

// fp16 operand storage (allocation-free rule: __device__ globals)
__device__ __half g_x[3*IN_ELEMS];                     // inputs q,k,v (single)
__device__ __half g_wh[4*W_ELEMS], g_wl[4*W_ELEMS];    // weights hi/lo
__device__ __half g_q[IN_ELEMS];                       // (b,h,s,d) single
__device__ __half g_kh[IN_ELEMS], g_kl[IN_ELEMS];      // (b,h,s,d) hi/lo
__device__ __half g_vth[IN_ELEMS], g_vtl[IN_ELEMS];    // (b,h,d,s) hi/lo
__device__ __half g_ctx[IN_ELEMS];                     // (b,s,e) single
__device__ float g_inv[Bn*Hn*Sn];                      // softmax 1/rowsum

// ---------------- PTX primitives ----------------
__device__ __forceinline__ uint32_t smem_u32(const void* p) {
    uint32_t a;
    asm("{ .reg .u64 t; cvta.to.shared.u64 t, %1; cvt.u32.u64 %0, t; }" : "=r"(a) : "l"(p));
    return a;
}
__device__ __forceinline__ void cpa16(uint32_t sdst, const void* gsrc) {
    asm volatile("cp.async.cg.shared.global [%0], [%1], 16;" :: "r"(sdst), "l"(gsrc));
}
#define CP_COMMIT() asm volatile("cp.async.commit_group;" ::: "memory")
#define CP_WAIT(N)  asm volatile("cp.async.wait_group %0;" :: "n"(N) : "memory")

#define LDSM4(R, A) asm volatile("ldmatrix.sync.aligned.m8n8.x4.shared.b16 {%0,%1,%2,%3}, [%4];" \
    : "=r"((R)[0]), "=r"((R)[1]), "=r"((R)[2]), "=r"((R)[3]) : "r"(A))

__device__ __forceinline__ void mma_f16(float c[4], const uint32_t a[4],
                                        uint32_t b0, uint32_t b1) {
    asm volatile(
        "mma.sync.aligned.m16n8k16.row.col.f32.f16.f16.f32 "
        "{%0,%1,%2,%3}, {%4,%5,%6,%7}, {%8,%9}, {%0,%1,%2,%3};"
        : "+f"(c[0]), "+f"(c[1]), "+f"(c[2]), "+f"(c[3])
        : "r"(a[0]), "r"(a[1]), "r"(a[2]), "r"(a[3]), "r"(b0), "r"(b1));
}

__device__ __forceinline__ uint32_t packh2(float a, float b) {
    __half2 h = __floats2half2_rn(a, b);
    return *(uint32_t*)&h;
}
__device__ __forceinline__ void split1(float x, __half& hi, __half& lo) {
    hi = __float2half_rn(x);
    lo = __float2half_rn(x - __half2float(hi));
}

// ---------------------------------------------------------------------------
// split_kernel: inputs -> fp16 single; weights -> fp16 hi/lo. grid (8192, 7)
// ---------------------------------------------------------------------------
__global__ void __launch_bounds__(256) split_kernel(
    const float* __restrict__ xq, const float* __restrict__ xk, const float* __restrict__ xv,
    const float* __restrict__ wq, const float* __restrict__ wk,
    const float* __restrict__ wv, const float* __restrict__ wo)
{
    const int z = blockIdx.y;
    int i = blockIdx.x * 256 + threadIdx.x;
    if (z < 3) {
        if (i >= IN_ELEMS / 4) return;
        const float* src = (z == 0) ? xq : ((z == 1) ? xk : xv);
        float4 v = ((const float4*)src)[i];
        uint2 o;
        o.x = packh2(v.x, v.y); o.y = packh2(v.z, v.w);
        ((uint2*)(g_x + (size_t)z * IN_ELEMS))[i] = o;
    } else {
        if (i >= W_ELEMS / 4) return;
        const float* src = (z == 3) ? wq : ((z == 4) ? wk : ((z == 5) ? wv : wo));
        float4 v = ((const float4*)src)[i];
        __half h0, l0, h1, l1, h2, l2, h3, l3;
        split1(v.x, h0, l0); split1(v.y, h1, l1);
        split1(v.z, h2, l2); split1(v.w, h3, l3);
        uint2 hi, lo;
        hi.x = packh2(__half2float(h0), __half2float(h1));
        hi.y = packh2(__half2float(h2), __half2float(h3));
        lo.x = packh2(__half2float(l0), __half2float(l1));
        lo.y = packh2(__half2float(l2), __half2float(l3));
        ((uint2*)(g_wh + (size_t)(z - 3) * W_ELEMS))[i] = hi;
        ((uint2*)(g_wl + (size_t)(z - 3) * W_ELEMS))[i] = lo;
    }
}

// ---------------------------------------------------------------------------
// 2-term warp MMA, K=32 chunk, warp tile 64x32, REORDERED so same-acc
// reuse distance is 8 MMAs (64 cyc > HMMA latency).
// ---------------------------------------------------------------------------
__device__ __forceinline__ void chunk2(uint32_t A, uint32_t Bh, uint32_t Bl,
                                       int arow, int bcol, int lane,
                                       float acc[4][4][4]) {
    const int hb = (lane >> 3) & 3;
    const uint32_t abase = (uint32_t)((arow + (lane & 15)) * 80 + (lane >> 4) * 16);
    const uint32_t bbase = (uint32_t)((bcol + (hb >> 1) * 8 + (lane & 7)) * 80 + (hb & 1) * 16);
    #pragma unroll
    for (int ks = 0; ks < 2; ks++) {
        uint32_t a[4][4];
        #pragma unroll
        for (int mt = 0; mt < 4; mt++)
            LDSM4(a[mt], A + abase + mt * 16 * 80 + ks * 32);
        #pragma unroll
        for (int np = 0; np < 2; np++) {
            uint32_t bh4[4], bl4[4];
            LDSM4(bh4, Bh + bbase + np * 16 * 80 + ks * 32);
            LDSM4(bl4, Bl + bbase + np * 16 * 80 + ks * 32);
            #pragma unroll
            for (int mt = 0; mt < 4; mt++) mma_f16(acc[mt][2*np],   a[mt], bh4[0], bh4[1]);
            #pragma unroll
            for (int mt = 0; mt < 4; mt++) mma_f16(acc[mt][2*np+1], a[mt], bh4[2], bh4[3]);
            #pragma unroll
            for (int mt = 0; mt < 4; mt++) mma_f16(acc[mt][2*np],   a[mt], bl4[0], bl4[1]);
            #pragma unroll
            for (int mt = 0; mt < 4; mt++) mma_f16(acc[mt][2*np+1], a[mt], bl4[2], bl4[3]);
        }
    }
}

// ---------------------------------------------------------------------------
// 128x128 GEMM, K=1024, 2-stage cp.async, single sync per chunk.
// ---------------------------------------------------------------------------
#define PSTG 30720
#define GEMM_SMEM (2*PSTG)

__device__ __forceinline__ void gissue(uint32_t sbase,
    const __half* A, const __half* Bh, const __half* Bl, int tid)
{
    #pragma unroll 2
    for (int idx = tid; idx < 512; idx += 256) {
        int r = idx >> 2, f = idx & 3;
        uint32_t so = (uint32_t)(r * 80 + f * 16);
        size_t go = (size_t)r * 1024 + f * 8;
        cpa16(sbase + so,         A + go);
        cpa16(sbase + 10240 + so, Bh + go);
        cpa16(sbase + 20480 + so, Bl + go);
    }
}

template<typename EPI>
__device__ __forceinline__ void gemm128(
    const __half* A, const __half* Bh, const __half* Bl, int tid, EPI epi)
{
    extern __shared__ char sm[];
    const uint32_t sb = smem_u32(sm);
    const int lane = tid & 31, wid = tid >> 5;
    const int wm = wid & 1, wn = wid >> 1;   // 2 x 4 warp grid

    float acc[4][4][4];
    #pragma unroll
    for (int i = 0; i < 4; i++)
        #pragma unroll
        for (int j = 0; j < 4; j++)
            #pragma unroll
            for (int l = 0; l < 4; l++) acc[i][j][l] = 0.f;

    gissue(sb, A, Bh, Bl, tid);
    CP_COMMIT();
    for (int c = 0; c < 32; c++) {
        CP_WAIT(0);
        __syncthreads();
        if (c + 1 < 32) {
            gissue(sb + ((c + 1) & 1) * PSTG,
                   A + (c + 1) * 32, Bh + (c + 1) * 32, Bl + (c + 1) * 32, tid);
            CP_COMMIT();
        }
        uint32_t s = sb + (c & 1) * PSTG;
        chunk2(s, s + 10240, s + 20480, wm * 64, wn * 32, lane, acc);
    }
    epi(acc, wm, wn, lane);
}

// ---------------------------------------------------------------------------
// Kernel: QKV projections. grid (8, 64, 3)
// ---------------------------------------------------------------------------
__global__ void __launch_bounds__(256, 2) proj_kernel(
    const float* __restrict__ qb, const float* __restrict__ kb, const float* __restrict__ vb)
{
    const int z = blockIdx.z;
    const int tid = threadIdx.x;
    const int m0 = blockIdx.y * 128, n0 = blockIdx.x * 128;
    const __half* A  = g_x  + (size_t)z * IN_ELEMS + (size_t)m0 * 1024;
    const __half* Bh = g_wh + (size_t)z * W_ELEMS + (size_t)n0 * 1024;
    const __half* Bl = g_wl + (size_t)z * W_ELEMS + (size_t)n0 * 1024;
    const float* bias = (z == 0) ? qb : ((z == 1) ? kb : vb);

    gemm128(A, Bh, Bl, tid,
        [&](float acc[4][4][4], int wm, int wn, int lane) {
            const int g = lane >> 2, t = lane & 3;
            #pragma unroll
            for (int mt = 0; mt < 4; mt++) {
                int m = m0 + wm * 64 + mt * 16 + g;
                int bb = m >> 10, s = m & 1023;
                #pragma unroll
                for (int nt = 0; nt < 4; nt++) {
                    int n = n0 + wn * 32 + nt * 8 + t * 2;
                    int h = n >> 6, d = n & 63;
                    float2 bv = *(const float2*)(bias + n);
                    float c0 = acc[mt][nt][0] + bv.x, c1 = acc[mt][nt][1] + bv.y;
                    float c2 = acc[mt][nt][2] + bv.x, c3 = acc[mt][nt][3] + bv.y;
                    if (z == 0) {
                        size_t a0 = (((size_t)bb * Hn + h) * Sn + s) * Dn + d;
                        *(uint32_t*)(g_q + a0)          = packh2(c0, c1);
                        *(uint32_t*)(g_q + a0 + 8 * Dn) = packh2(c2, c3);
                    } else if (z == 1) {
                        size_t a0 = (((size_t)bb * Hn + h) * Sn + s) * Dn + d;
                        __half h0,l0,h1,l1,h2,l2,h3,l3;
                        split1(c0,h0,l0); split1(c1,h1,l1);
                        split1(c2,h2,l2); split1(c3,h3,l3);
                        *(uint32_t*)(g_kh + a0) = packh2(__half2float(h0), __half2float(h1));
                        *(uint32_t*)(g_kl + a0) = packh2(__half2float(l0), __half2float(l1));
                        *(uint32_t*)(g_kh + a0 + 8 * Dn) = packh2(__half2float(h2), __half2float(h3));
                        *(uint32_t*)(g_kl + a0 + 8 * Dn) = packh2(__half2float(l2), __half2float(l3));
                    } else {
                        size_t a0 = (((size_t)bb * Hn + h) * Dn + d) * Sn + s;
                        __half h0,l0,h1,l1,h2,l2,h3,l3;
                        split1(c0,h0,l0); split1(c1,h1,l1);
                        split1(c2,h2,l2); split1(c3,h3,l3);
                        g_vth[a0] = h0;          g_vtl[a0] = l0;
                        g_vth[a0 + Sn] = h1;     g_vtl[a0 + Sn] = l1;
                        g_vth[a0 + 8] = h2;      g_vtl[a0 + 8] = l2;
                        g_vth[a0 + Sn + 8] = h3; g_vtl[a0 + Sn + 8] = l3;
                    }
                }
            }
        });
}

// ---------------------------------------------------------------------------
// Pass 1: softmax row sums (single-term fp16 scores). grid (8, 128)
// ---------------------------------------------------------------------------
#define SQ 0
#define SKH(st) (18432 + (st)*9216)
#define SSUM 36864
#define SUM_SMEM 37376

__global__ void __launch_bounds__(256, 2) sum_kernel()
{
    extern __shared__ char sm[];
    const uint32_t sb = smem_u32(sm);
    float* sums = (float*)(sm + SSUM);

    const int tid = threadIdx.x, lane = tid & 31, w = tid >> 5;
    const int g = lane >> 2, t = lane & 3;
    const int wr = w * 16;
    const int hb = (lane >> 3) & 3;
    const int m0 = blockIdx.x * 128;
    const int bh = blockIdx.y;

    const __half* Qg  = g_q  + ((size_t)bh * Sn + m0) * Dn;
    const __half* Khg = g_kh + (size_t)bh * Sn * Dn;

    auto issueK = [&](int c, int st) {
        uint32_t base = sb + SKH(st);
        #pragma unroll
        for (int j = 0; j < 2; j++) {
            int idx = tid + j * 256;
            int r = idx >> 3, f = idx & 7;
            cpa16(base + r * 144 + f * 16, Khg + (size_t)(c * 64 + r) * Dn + f * 8);
        }
    };

    #pragma unroll
    for (int j = 0; j < 4; j++) {
        int idx = tid + j * 256;
        int r = idx >> 3, f = idx & 7;
        cpa16(sb + SQ + r * 144 + f * 16, Qg + (size_t)r * Dn + f * 8);
    }
    issueK(0, 0);
    CP_COMMIT();

    float rs0 = 0.f, rs1 = 0.f;
    for (int c = 0; c < 16; c++) {
        CP_WAIT(0);
        __syncthreads();
        if (c + 1 < 16) { issueK(c + 1, (c + 1) & 1); CP_COMMIT(); }
        const uint32_t stg = sb + SKH(c & 1);

        float sa[8][4];
        #pragma unroll
        for (int i = 0; i < 8; i++)
            #pragma unroll
            for (int l = 0; l < 4; l++) sa[i][l] = 0.f;
        #pragma unroll
        for (int ks = 0; ks < 4; ks++) {
            uint32_t qa[4];
            LDSM4(qa, sb + SQ + (wr + (lane & 15)) * 144 + (lane >> 4) * 16 + ks * 32);
            #pragma unroll
            for (int np = 0; np < 4; np++) {
                uint32_t bo = (uint32_t)((np * 16 + (hb >> 1) * 8 + (lane & 7)) * 144
                                         + (hb & 1) * 16 + ks * 32);
                uint32_t kh4[4];
                LDSM4(kh4, stg + bo);
                mma_f16(sa[2*np],   qa, kh4[0], kh4[1]);
                mma_f16(sa[2*np+1], qa, kh4[2], kh4[3]);
            }
        }
        #pragma unroll
        for (int j = 0; j < 8; j++) {
            rs0 += __expf(sa[j][0] * 0.125f) + __expf(sa[j][1] * 0.125f);
            rs1 += __expf(sa[j][2] * 0.125f) + __expf(sa[j][3] * 0.125f);
        }
    }

    rs0 += __shfl_xor_sync(0xffffffffu, rs0, 1);
    rs0 += __shfl_xor_sync(0xffffffffu, rs0, 2);
    rs1 += __shfl_xor_sync(0xffffffffu, rs1, 1);
    rs1 += __shfl_xor_sync(0xffffffffu, rs1, 2);
    if (t == 0) { sums[wr + g] = rs0; sums[wr + g + 8] = rs1; }
    __syncthreads();
    if (tid < 128)
        g_inv[((size_t)bh << 10) + m0 + tid] = 1.0f / sums[tid];
}

// ---------------------------------------------------------------------------
// Pass 2: fused attention. Warp grid 4m x 2n (32 rows x 32 keys per warp):
// K/V fragment loads halved vs R9 (was the L1=83% bottleneck). Each warp
// accumulates partial O over its key half; merged via one smem reduction.
// grid (8, 128). smem: Q@0 (18432) | stage st @ 18432+st*36864:
//   KH+0 KL+9216 VH+18432 VL+27648. O-reduction reuses stage 0. Total 92160.
// ---------------------------------------------------------------------------
#define FQ 0
#define FST(st) (18432 + (st)*36864)
#define FUSED_SMEM 92160

__global__ void __launch_bounds__(256) fused_attn_kernel(float* __restrict__ attn)
{
    extern __shared__ char sm[];
    const uint32_t sb = smem_u32(sm);

    const int tid = threadIdx.x, lane = tid & 31, w = tid >> 5;
    const int g = lane >> 2, t = lane & 3;
    const int wm = w & 3, wn = w >> 2;      // 4 m-warps x 2 n-warps
    const int wr = wm * 32;
    const int hb = (lane >> 3) & 3;
    const int m0 = blockIdx.x * 128;
    const int bh = blockIdx.y;

    const __half* Qg  = g_q   + ((size_t)bh * Sn + m0) * Dn;
    const __half* Khg = g_kh  + (size_t)bh * Sn * Dn;
    const __half* Klg = g_kl  + (size_t)bh * Sn * Dn;
    const __half* Vhg = g_vth + (size_t)bh * Dn * Sn;
    const __half* Vlg = g_vtl + (size_t)bh * Dn * Sn;
    float* attnB = attn + ((size_t)bh * Sn + m0) * Sn;

    // per-thread row inverses (rows wr+mt*16+g and +8)
    const float* invb = g_inv + ((size_t)bh << 10) + m0 + wr;
    float ivA[2], ivB[2];
    ivA[0] = invb[g];       ivB[0] = invb[g + 8];
    ivA[1] = invb[16 + g];  ivB[1] = invb[16 + 8 + g];

    auto issueKV = [&](int c, int st) {
        uint32_t base = sb + FST(st);
        #pragma unroll
        for (int j = 0; j < 2; j++) {
            int idx = tid + j * 256;
            int r = idx >> 3, f = idx & 7;
            size_t go = (size_t)(c * 64 + r) * Dn + f * 8;
            cpa16(base + r * 144 + f * 16,        Khg + go);
            cpa16(base + 9216 + r * 144 + f * 16, Klg + go);
        }
        #pragma unroll
        for (int j = 0; j < 2; j++) {
            int idx = tid + j * 256;
            int d = idx >> 3, f = idx & 7;
            size_t go = (size_t)d * Sn + c * 64 + f * 8;
            cpa16(base + 18432 + d * 144 + f * 16, Vhg + go);
            cpa16(base + 27648 + d * 144 + f * 16, Vlg + go);
        }
    };

    #pragma unroll
    for (int j = 0; j < 4; j++) {
        int idx = tid + j * 256;
        int r = idx >> 3, f = idx & 7;
        cpa16(sb + FQ + r * 144 + f * 16, Qg + (size_t)r * Dn + f * 8);
    }
    issueKV(0, 0);
    CP_COMMIT();

    float O[2][8][4];
    #pragma unroll
    for (int i = 0; i < 2; i++)
        #pragma unroll
        for (int j = 0; j < 8; j++)
            #pragma unroll
            for (int l = 0; l < 4; l++) O[i][j][l] = 0.f;

    for (int c = 0; c < 16; c++) {
        CP_WAIT(0);
        __syncthreads();
        if (c + 1 < 16) { issueKV(c + 1, (c + 1) & 1); CP_COMMIT(); }
        const uint32_t stg = sb + FST(c & 1);

        // ---- S = Q K^T : warp covers rows wr..wr+32, keys wn*32..+32 ----
        float sa[2][4][4];
        #pragma unroll
        for (int i = 0; i < 2; i++)
            #pragma unroll
            for (int j = 0; j < 4; j++)
                #pragma unroll
                for (int l = 0; l < 4; l++) sa[i][j][l] = 0.f;
        #pragma unroll
        for (int ks = 0; ks < 4; ks++) {
            uint32_t qa[2][4];
            uint32_t qo = sb + FQ + (wr + (lane & 15)) * 144 + (lane >> 4) * 16 + ks * 32;
            LDSM4(qa[0], qo);
            LDSM4(qa[1], qo + 16 * 144);
            #pragma unroll
            for (int np = 0; np < 2; np++) {
                uint32_t bo = (uint32_t)((wn * 32 + np * 16 + (hb >> 1) * 8 + (lane & 7)) * 144
                                         + (hb & 1) * 16 + ks * 32);
                uint32_t kh4[4], kl4[4];
                LDSM4(kh4, stg + bo);
                LDSM4(kl4, stg + 9216 + bo);
                mma_f16(sa[0][2*np],   qa[0], kh4[0], kh4[1]);
                mma_f16(sa[1][2*np],   qa[1], kh4[0], kh4[1]);
                mma_f16(sa[0][2*np+1], qa[0], kh4[2], kh4[3]);
                mma_f16(sa[1][2*np+1], qa[1], kh4[2], kh4[3]);
                mma_f16(sa[0][2*np],   qa[0], kl4[0], kl4[1]);
                mma_f16(sa[1][2*np],   qa[1], kl4[0], kl4[1]);
                mma_f16(sa[0][2*np+1], qa[0], kl4[2], kl4[3]);
                mma_f16(sa[1][2*np+1], qa[1], kl4[2], kl4[3]);
            }
        }
        // ---- normalized exp + final attn write ----
        const int cb = c * 64 + wn * 32;
        #pragma unroll
        for (int mt = 0; mt < 2; mt++) {
            float* r0 = attnB + (size_t)(wr + mt * 16 + g) * Sn + cb;
            float* r1 = attnB + (size_t)(wr + mt * 16 + g + 8) * Sn + cb;
            #pragma unroll
            for (int nt = 0; nt < 4; nt++) {
                float e0 = __expf(sa[mt][nt][0] * 0.125f) * ivA[mt];
                float e1 = __expf(sa[mt][nt][1] * 0.125f) * ivA[mt];
                float e2 = __expf(sa[mt][nt][2] * 0.125f) * ivB[mt];
                float e3 = __expf(sa[mt][nt][3] * 0.125f) * ivB[mt];
                *(float2*)(r0 + nt * 8 + t * 2) = make_float2(e0, e1);
                *(float2*)(r1 + nt * 8 + t * 2) = make_float2(e2, e3);
                sa[mt][nt][0] = e0; sa[mt][nt][1] = e1;
                sa[mt][nt][2] = e2; sa[mt][nt][3] = e3;
            }
        }
        // ---- repack normalized P -> PV A-frags ----
        uint32_t PA[2][2][4];
        #pragma unroll
        for (int mt = 0; mt < 2; mt++)
            #pragma unroll
            for (int np = 0; np < 2; np++) {
                PA[mt][np][0] = packh2(sa[mt][2*np][0],   sa[mt][2*np][1]);
                PA[mt][np][1] = packh2(sa[mt][2*np][2],   sa[mt][2*np][3]);
                PA[mt][np][2] = packh2(sa[mt][2*np+1][0], sa[mt][2*np+1][1]);
                PA[mt][np][3] = packh2(sa[mt][2*np+1][2], sa[mt][2*np+1][3]);
            }
        // ---- O += P V over warp's 32 keys ----
        #pragma unroll
        for (int kp = 0; kp < 2; kp++) {
            #pragma unroll
            for (int npd = 0; npd < 4; npd++) {
                uint32_t bo = (uint32_t)((npd * 16 + (hb >> 1) * 8 + (lane & 7)) * 144
                                         + (hb & 1) * 16 + (wn * 2 + kp) * 32);
                uint32_t vh4[4], vl4[4];
                LDSM4(vh4, stg + 18432 + bo);
                LDSM4(vl4, stg + 27648 + bo);
                mma_f16(O[0][2*npd],   PA[0][kp], vh4[0], vh4[1]);
                mma_f16(O[1][2*npd],   PA[1][kp], vh4[0], vh4[1]);
                mma_f16(O[0][2*npd+1], PA[0][kp], vh4[2], vh4[3]);
                mma_f16(O[1][2*npd+1], PA[1][kp], vh4[2], vh4[3]);
                mma_f16(O[0][2*npd],   PA[0][kp], vl4[0], vl4[1]);
                mma_f16(O[1][2*npd],   PA[1][kp], vl4[0], vl4[1]);
                mma_f16(O[0][2*npd+1], PA[0][kp], vl4[2], vl4[3]);
                mma_f16(O[1][2*npd+1], PA[1][kp], vl4[2], vl4[3]);
            }
        }
    }

    // ---- merge the two key-half partials via smem, write ctx ----
    __syncthreads();                        // all stage reads done; reuse FST(0)
    float* red = (float*)(sm + FST(0));     // 128 rows x 64 d = 32 KB
    if (wn == 1) {
        #pragma unroll
        for (int mt = 0; mt < 2; mt++)
            #pragma unroll
            for (int nt = 0; nt < 8; nt++) {
                int b0 = (wr + mt * 16 + g) * 64 + nt * 8 + t * 2;
                int b1 = (wr + mt * 16 + g + 8) * 64 + nt * 8 + t * 2;
                *(float2*)(red + b0) = make_float2(O[mt][nt][0], O[mt][nt][1]);
                *(float2*)(red + b1) = make_float2(O[mt][nt][2], O[mt][nt][3]);
            }
    }
    __syncthreads();
    if (wn == 0) {
        const int bb = bh >> 4, h = bh & 15;
        #pragma unroll
        for (int mt = 0; mt < 2; mt++) {
            int m = m0 + wr + mt * 16 + g;
            __half* c0 = g_ctx + ((size_t)(bb * Sn + m)) * En + h * Dn;
            __half* c1 = g_ctx + ((size_t)(bb * Sn + m + 8)) * En + h * Dn;
            #pragma unroll
            for (int nt = 0; nt < 8; nt++) {
                int b0 = (wr + mt * 16 + g) * 64 + nt * 8 + t * 2;
                int b1 = (wr + mt * 16 + g + 8) * 64 + nt * 8 + t * 2;
                float2 p0 = *(float2*)(red + b0);
                float2 p1 = *(float2*)(red + b1);
                int d = nt * 8 + t * 2;
                *(uint32_t*)(c0 + d) = packh2(O[mt][nt][0] + p0.x, O[mt][nt][1] + p0.y);
                *(uint32_t*)(c1 + d) = packh2(O[mt][nt][2] + p1.x, O[mt][nt][3] + p1.y);
            }
        }
    }
}

// ---------------------------------------------------------------------------
// Kernel: output projection. grid (8, 64)
// ---------------------------------------------------------------------------
__global__ void __launch_bounds__(256, 2) outproj_kernel(
    const float* __restrict__ ob, float* __restrict__ Out)
{
    const int tid = threadIdx.x;
    const int m0 = blockIdx.y * 128, n0 = blockIdx.x * 128;
    const __half* A  = g_ctx + (size_t)m0 * 1024;
    const __half* Bh = g_wh + (size_t)3 * W_ELEMS + (size_t)n0 * 1024;
    const __half* Bl = g_wl + (size_t)3 * W_ELEMS + (size_t)n0 * 1024;

    gemm128(A, Bh, Bl, tid,
        [&](float acc[4][4][4], int wm, int wn, int lane) {
            const int g = lane >> 2, t = lane & 3;
            #pragma unroll
            for (int mt = 0; mt < 4; mt++) {
                int m = m0 + wm * 64 + mt * 16 + g;
                float* orow = Out + (size_t)m * En;
                #pragma unroll
                for (int nt = 0; nt < 4; nt++) {
                    int n = n0 + wn * 32 + nt * 8 + t * 2;
                    float2 bv = *(const float2*)(ob + n);
                    *(float2*)(orow + n) =
                        make_float2(acc[mt][nt][0] + bv.x, acc[mt][nt][1] + bv.y);
                    *(float2*)(orow + 8 * En + n) =
                        make_float2(acc[mt][nt][2] + bv.x, acc[mt][nt][3] + bv.y);
                }
            }
        });
}

// ---------------------------------------------------------------------------
extern "C" void kernel_launch(void* const* d_in, const int* in_sizes, int n_in,
                              void* d_out, int out_size)
{
    const float* q_in  = (const float*)d_in[0];
    const float* k_in  = (const float*)d_in[1];
    const float* v_in  = (const float*)d_in[2];
    const float* q_w   = (const float*)d_in[3];
    const float* q_b   = (const float*)d_in[4];
    const float* k_w   = (const float*)d_in[5];
    const float* k_b   = (const float*)d_in[6];
    const float* v_w   = (const float*)d_in[7];
    const float* v_b   = (const float*)d_in[8];
    const float* out_w = (const float*)d_in[9];
    const float* out_b = (const float*)d_in[10];

    float* out  = (float*)d_out;
    float* attn = out;                  // (B,H,S,S)
    float* outp = out + ATTN_ELEMS;     // (B,S,E)

    cudaFuncSetAttribute(proj_kernel,       cudaFuncAttributeMaxDynamicSharedMemorySize, GEMM_SMEM);
    cudaFuncSetAttribute(sum_kernel,        cudaFuncAttributeMaxDynamicSharedMemorySize, SUM_SMEM);
    cudaFuncSetAttribute(fused_attn_kernel, cudaFuncAttributeMaxDynamicSharedMemorySize, FUSED_SMEM);
    cudaFuncSetAttribute(outproj_kernel,    cudaFuncAttributeMaxDynamicSharedMemorySize, GEMM_SMEM);

    split_kernel<<<dim3(8192, 7), 256>>>(q_in, k_in, v_in, q_w, k_w, v_w, out_w);
    proj_kernel<<<dim3(8, 64, 3), 256, GEMM_SMEM>>>(q_b, k_b, v_b);
    sum_kernel<<<dim3(8, 128), 256, SUM_SMEM>>>();
    fused_attn_kernel<<<dim3(8, 128), 256, FUSED_SMEM>>>(attn);
    outproj_kernel<<<dim3(8, 64), 256, GEMM_SMEM>>>(out_b, outp);
}

// round 11
// speedup vs baseline: 1.0227x; 1.0227x over previous
#include <cuda_runtime.h>
#include <cuda_fp16.h>
#include <cstdint>

#define Bn 8
#define Sn 1024
#define En 1024
#define Hn 16
#define Dn 64
#define ATTN_ELEMS ((size_t)Bn*Hn*Sn*Sn)
#define IN_ELEMS (Bn*Sn*En)     // 8388608
#define W_ELEMS  (En*En)        // 1048576

// fp16 operand storage (allocation-free rule: __device__ globals)
__device__ __half g_x[3*IN_ELEMS];                     // inputs q,k,v (single)
__device__ __half g_wh[4*W_ELEMS], g_wl[4*W_ELEMS];    // weights hi/lo
__device__ __half g_q[IN_ELEMS];                       // (b,h,s,d) single
__device__ __half g_kh[IN_ELEMS], g_kl[IN_ELEMS];      // (b,h,s,d) hi/lo
__device__ __half g_vth[IN_ELEMS], g_vtl[IN_ELEMS];    // (b,h,d,s) hi/lo
__device__ __half g_ctx[IN_ELEMS];                     // (b,s,e) single
__device__ float g_inv[Bn*Hn*Sn];                      // softmax 1/rowsum

// ---------------- PTX primitives ----------------
__device__ __forceinline__ uint32_t smem_u32(const void* p) {
    uint32_t a;
    asm("{ .reg .u64 t; cvta.to.shared.u64 t, %1; cvt.u32.u64 %0, t; }" : "=r"(a) : "l"(p));
    return a;
}
__device__ __forceinline__ void cpa16(uint32_t sdst, const void* gsrc) {
    asm volatile("cp.async.cg.shared.global [%0], [%1], 16;" :: "r"(sdst), "l"(gsrc));
}
#define CP_COMMIT() asm volatile("cp.async.commit_group;" ::: "memory")
#define CP_WAIT(N)  asm volatile("cp.async.wait_group %0;" :: "n"(N) : "memory")

#define LDSM4(R, A) asm volatile("ldmatrix.sync.aligned.m8n8.x4.shared.b16 {%0,%1,%2,%3}, [%4];" \
    : "=r"((R)[0]), "=r"((R)[1]), "=r"((R)[2]), "=r"((R)[3]) : "r"(A))

__device__ __forceinline__ void mma_f16(float c[4], const uint32_t a[4],
                                        uint32_t b0, uint32_t b1) {
    asm volatile(
        "mma.sync.aligned.m16n8k16.row.col.f32.f16.f16.f32 "
        "{%0,%1,%2,%3}, {%4,%5,%6,%7}, {%8,%9}, {%0,%1,%2,%3};"
        : "+f"(c[0]), "+f"(c[1]), "+f"(c[2]), "+f"(c[3])
        : "r"(a[0]), "r"(a[1]), "r"(a[2]), "r"(a[3]), "r"(b0), "r"(b1));
}

__device__ __forceinline__ uint32_t packh2(float a, float b) {
    __half2 h = __floats2half2_rn(a, b);
    return *(uint32_t*)&h;
}
__device__ __forceinline__ void split1(float x, __half& hi, __half& lo) {
    hi = __float2half_rn(x);
    lo = __float2half_rn(x - __half2float(hi));
}

// ---------------------------------------------------------------------------
// split_kernel: inputs -> fp16 single; weights -> fp16 hi/lo. grid (8192, 7)
// ---------------------------------------------------------------------------
__global__ void __launch_bounds__(256) split_kernel(
    const float* __restrict__ xq, const float* __restrict__ xk, const float* __restrict__ xv,
    const float* __restrict__ wq, const float* __restrict__ wk,
    const float* __restrict__ wv, const float* __restrict__ wo)
{
    const int z = blockIdx.y;
    int i = blockIdx.x * 256 + threadIdx.x;
    if (z < 3) {
        if (i >= IN_ELEMS / 4) return;
        const float* src = (z == 0) ? xq : ((z == 1) ? xk : xv);
        float4 v = ((const float4*)src)[i];
        uint2 o;
        o.x = packh2(v.x, v.y); o.y = packh2(v.z, v.w);
        ((uint2*)(g_x + (size_t)z * IN_ELEMS))[i] = o;
    } else {
        if (i >= W_ELEMS / 4) return;
        const float* src = (z == 3) ? wq : ((z == 4) ? wk : ((z == 5) ? wv : wo));
        float4 v = ((const float4*)src)[i];
        __half h0, l0, h1, l1, h2, l2, h3, l3;
        split1(v.x, h0, l0); split1(v.y, h1, l1);
        split1(v.z, h2, l2); split1(v.w, h3, l3);
        uint2 hi, lo;
        hi.x = packh2(__half2float(h0), __half2float(h1));
        hi.y = packh2(__half2float(h2), __half2float(h3));
        lo.x = packh2(__half2float(l0), __half2float(l1));
        lo.y = packh2(__half2float(l2), __half2float(l3));
        ((uint2*)(g_wh + (size_t)(z - 3) * W_ELEMS))[i] = hi;
        ((uint2*)(g_wl + (size_t)(z - 3) * W_ELEMS))[i] = lo;
    }
}

// ---------------------------------------------------------------------------
// 2-term warp MMA on a K=32 chunk (A single, B hi/lo), stride 80.
// Warp tile 64 rows x 32 cols. R9 instruction order (measured best).
// ---------------------------------------------------------------------------
__device__ __forceinline__ void chunk2(uint32_t A, uint32_t Bh, uint32_t Bl,
                                       int arow, int bcol, int lane,
                                       float acc[4][4][4]) {
    const int hb = (lane >> 3) & 3;
    const uint32_t abase = (uint32_t)((arow + (lane & 15)) * 80 + (lane >> 4) * 16);
    const uint32_t bbase = (uint32_t)((bcol + (hb >> 1) * 8 + (lane & 7)) * 80 + (hb & 1) * 16);
    #pragma unroll
    for (int ks = 0; ks < 2; ks++) {
        uint32_t a[4][4];
        #pragma unroll
        for (int mt = 0; mt < 4; mt++)
            LDSM4(a[mt], A + abase + mt * 16 * 80 + ks * 32);
        #pragma unroll
        for (int np = 0; np < 2; np++) {
            uint32_t bh4[4], bl4[4];
            LDSM4(bh4, Bh + bbase + np * 16 * 80 + ks * 32);
            LDSM4(bl4, Bl + bbase + np * 16 * 80 + ks * 32);
            #pragma unroll
            for (int mt = 0; mt < 4; mt++) {
                mma_f16(acc[mt][2*np],   a[mt], bh4[0], bh4[1]);
                mma_f16(acc[mt][2*np],   a[mt], bl4[0], bl4[1]);
                mma_f16(acc[mt][2*np+1], a[mt], bh4[2], bh4[3]);
                mma_f16(acc[mt][2*np+1], a[mt], bl4[2], bl4[3]);
            }
        }
    }
}

// ---------------------------------------------------------------------------
// 128x128 GEMM, K=1024, 2-stage cp.async, single sync per chunk.
// ---------------------------------------------------------------------------
#define PSTG 30720
#define GEMM_SMEM (2*PSTG)

__device__ __forceinline__ void gissue(uint32_t sbase,
    const __half* A, const __half* Bh, const __half* Bl, int tid)
{
    #pragma unroll 2
    for (int idx = tid; idx < 512; idx += 256) {
        int r = idx >> 2, f = idx & 3;
        uint32_t so = (uint32_t)(r * 80 + f * 16);
        size_t go = (size_t)r * 1024 + f * 8;
        cpa16(sbase + so,         A + go);
        cpa16(sbase + 10240 + so, Bh + go);
        cpa16(sbase + 20480 + so, Bl + go);
    }
}

template<typename EPI>
__device__ __forceinline__ void gemm128(
    const __half* A, const __half* Bh, const __half* Bl, int tid, EPI epi)
{
    extern __shared__ char sm[];
    const uint32_t sb = smem_u32(sm);
    const int lane = tid & 31, wid = tid >> 5;
    const int wm = wid & 1, wn = wid >> 1;   // 2 x 4 warp grid

    float acc[4][4][4];
    #pragma unroll
    for (int i = 0; i < 4; i++)
        #pragma unroll
        for (int j = 0; j < 4; j++)
            #pragma unroll
            for (int l = 0; l < 4; l++) acc[i][j][l] = 0.f;

    gissue(sb, A, Bh, Bl, tid);
    CP_COMMIT();
    for (int c = 0; c < 32; c++) {
        CP_WAIT(0);
        __syncthreads();
        if (c + 1 < 32) {
            gissue(sb + ((c + 1) & 1) * PSTG,
                   A + (c + 1) * 32, Bh + (c + 1) * 32, Bl + (c + 1) * 32, tid);
            CP_COMMIT();
        }
        uint32_t s = sb + (c & 1) * PSTG;
        chunk2(s, s + 10240, s + 20480, wm * 64, wn * 32, lane, acc);
    }
    epi(acc, wm, wn, lane);
}

// ---------------------------------------------------------------------------
// Kernel: QKV projections. grid (8, 64, 3)
// ---------------------------------------------------------------------------
__global__ void __launch_bounds__(256, 2) proj_kernel(
    const float* __restrict__ qb, const float* __restrict__ kb, const float* __restrict__ vb)
{
    const int z = blockIdx.z;
    const int tid = threadIdx.x;
    const int m0 = blockIdx.y * 128, n0 = blockIdx.x * 128;
    const __half* A  = g_x  + (size_t)z * IN_ELEMS + (size_t)m0 * 1024;
    const __half* Bh = g_wh + (size_t)z * W_ELEMS + (size_t)n0 * 1024;
    const __half* Bl = g_wl + (size_t)z * W_ELEMS + (size_t)n0 * 1024;
    const float* bias = (z == 0) ? qb : ((z == 1) ? kb : vb);

    gemm128(A, Bh, Bl, tid,
        [&](float acc[4][4][4], int wm, int wn, int lane) {
            const int g = lane >> 2, t = lane & 3;
            #pragma unroll
            for (int mt = 0; mt < 4; mt++) {
                int m = m0 + wm * 64 + mt * 16 + g;
                int bb = m >> 10, s = m & 1023;
                #pragma unroll
                for (int nt = 0; nt < 4; nt++) {
                    int n = n0 + wn * 32 + nt * 8 + t * 2;
                    int h = n >> 6, d = n & 63;
                    float2 bv = *(const float2*)(bias + n);
                    float c0 = acc[mt][nt][0] + bv.x, c1 = acc[mt][nt][1] + bv.y;
                    float c2 = acc[mt][nt][2] + bv.x, c3 = acc[mt][nt][3] + bv.y;
                    if (z == 0) {
                        size_t a0 = (((size_t)bb * Hn + h) * Sn + s) * Dn + d;
                        *(uint32_t*)(g_q + a0)          = packh2(c0, c1);
                        *(uint32_t*)(g_q + a0 + 8 * Dn) = packh2(c2, c3);
                    } else if (z == 1) {
                        size_t a0 = (((size_t)bb * Hn + h) * Sn + s) * Dn + d;
                        __half h0,l0,h1,l1,h2,l2,h3,l3;
                        split1(c0,h0,l0); split1(c1,h1,l1);
                        split1(c2,h2,l2); split1(c3,h3,l3);
                        *(uint32_t*)(g_kh + a0) = packh2(__half2float(h0), __half2float(h1));
                        *(uint32_t*)(g_kl + a0) = packh2(__half2float(l0), __half2float(l1));
                        *(uint32_t*)(g_kh + a0 + 8 * Dn) = packh2(__half2float(h2), __half2float(h3));
                        *(uint32_t*)(g_kl + a0 + 8 * Dn) = packh2(__half2float(l2), __half2float(l3));
                    } else {
                        size_t a0 = (((size_t)bb * Hn + h) * Dn + d) * Sn + s;
                        __half h0,l0,h1,l1,h2,l2,h3,l3;
                        split1(c0,h0,l0); split1(c1,h1,l1);
                        split1(c2,h2,l2); split1(c3,h3,l3);
                        g_vth[a0] = h0;          g_vtl[a0] = l0;
                        g_vth[a0 + Sn] = h1;     g_vtl[a0 + Sn] = l1;
                        g_vth[a0 + 8] = h2;      g_vtl[a0 + 8] = l2;
                        g_vth[a0 + Sn + 8] = h3; g_vtl[a0 + Sn + 8] = l3;
                    }
                }
            }
        });
}

// ---------------------------------------------------------------------------
// Pass 1: softmax row sums (single-term fp16 scores). grid (8, 128)
// ---------------------------------------------------------------------------
#define SQ 0
#define SKH(st) (18432 + (st)*9216)
#define SSUM 36864
#define SUM_SMEM 37376

__global__ void __launch_bounds__(256, 2) sum_kernel()
{
    extern __shared__ char sm[];
    const uint32_t sb = smem_u32(sm);
    float* sums = (float*)(sm + SSUM);

    const int tid = threadIdx.x, lane = tid & 31, w = tid >> 5;
    const int g = lane >> 2, t = lane & 3;
    const int wr = w * 16;
    const int hb = (lane >> 3) & 3;
    const int m0 = blockIdx.x * 128;
    const int bh = blockIdx.y;

    const __half* Qg  = g_q  + ((size_t)bh * Sn + m0) * Dn;
    const __half* Khg = g_kh + (size_t)bh * Sn * Dn;

    auto issueK = [&](int c, int st) {
        uint32_t base = sb + SKH(st);
        #pragma unroll
        for (int j = 0; j < 2; j++) {
            int idx = tid + j * 256;
            int r = idx >> 3, f = idx & 7;
            cpa16(base + r * 144 + f * 16, Khg + (size_t)(c * 64 + r) * Dn + f * 8);
        }
    };

    #pragma unroll
    for (int j = 0; j < 4; j++) {
        int idx = tid + j * 256;
        int r = idx >> 3, f = idx & 7;
        cpa16(sb + SQ + r * 144 + f * 16, Qg + (size_t)r * Dn + f * 8);
    }
    issueK(0, 0);
    CP_COMMIT();

    float rs0 = 0.f, rs1 = 0.f;
    for (int c = 0; c < 16; c++) {
        CP_WAIT(0);
        __syncthreads();
        if (c + 1 < 16) { issueK(c + 1, (c + 1) & 1); CP_COMMIT(); }
        const uint32_t stg = sb + SKH(c & 1);

        float sa[8][4];
        #pragma unroll
        for (int i = 0; i < 8; i++)
            #pragma unroll
            for (int l = 0; l < 4; l++) sa[i][l] = 0.f;
        #pragma unroll
        for (int ks = 0; ks < 4; ks++) {
            uint32_t qa[4];
            LDSM4(qa, sb + SQ + (wr + (lane & 15)) * 144 + (lane >> 4) * 16 + ks * 32);
            #pragma unroll
            for (int np = 0; np < 4; np++) {
                uint32_t bo = (uint32_t)((np * 16 + (hb >> 1) * 8 + (lane & 7)) * 144
                                         + (hb & 1) * 16 + ks * 32);
                uint32_t kh4[4];
                LDSM4(kh4, stg + bo);
                mma_f16(sa[2*np],   qa, kh4[0], kh4[1]);
                mma_f16(sa[2*np+1], qa, kh4[2], kh4[3]);
            }
        }
        #pragma unroll
        for (int j = 0; j < 8; j++) {
            rs0 += __expf(sa[j][0] * 0.125f) + __expf(sa[j][1] * 0.125f);
            rs1 += __expf(sa[j][2] * 0.125f) + __expf(sa[j][3] * 0.125f);
        }
    }

    rs0 += __shfl_xor_sync(0xffffffffu, rs0, 1);
    rs0 += __shfl_xor_sync(0xffffffffu, rs0, 2);
    rs1 += __shfl_xor_sync(0xffffffffu, rs1, 1);
    rs1 += __shfl_xor_sync(0xffffffffu, rs1, 2);
    if (t == 0) { sums[wr + g] = rs0; sums[wr + g + 8] = rs1; }
    __syncthreads();
    if (tid < 128)
        g_inv[((size_t)bh << 10) + m0 + tid] = 1.0f / sums[tid];
}

// ---------------------------------------------------------------------------
// Pass 2: fused attention. Warp grid 4m x 2n (32 rows x 32 keys per warp),
// the 32 keys processed in TWO 16-key groups so sa/PA register footprint
// halves (fits 128 regs -> __launch_bounds__(256,2) -> 2 CTAs/SM, no spill).
// grid (8, 128). smem: Q@0 (18432) | stage st @ 18432+st*36864:
//   KH+0 KL+9216 VH+18432 VL+27648. O-merge reuses stage 0. Total 92160.
// ---------------------------------------------------------------------------
#define FQ 0
#define FST(st) (18432 + (st)*36864)
#define FUSED_SMEM 92160

__global__ void __launch_bounds__(256, 2) fused_attn_kernel(float* __restrict__ attn)
{
    extern __shared__ char sm[];
    const uint32_t sb = smem_u32(sm);

    const int tid = threadIdx.x, lane = tid & 31, w = tid >> 5;
    const int g = lane >> 2, t = lane & 3;
    const int wm = w & 3, wn = w >> 2;      // 4 m-warps x 2 n-warps
    const int wr = wm * 32;
    const int hb = (lane >> 3) & 3;
    const int m0 = blockIdx.x * 128;
    const int bh = blockIdx.y;

    const __half* Qg  = g_q   + ((size_t)bh * Sn + m0) * Dn;
    const __half* Khg = g_kh  + (size_t)bh * Sn * Dn;
    const __half* Klg = g_kl  + (size_t)bh * Sn * Dn;
    const __half* Vhg = g_vth + (size_t)bh * Dn * Sn;
    const __half* Vlg = g_vtl + (size_t)bh * Dn * Sn;
    float* attnB = attn + ((size_t)bh * Sn + m0) * Sn;

    const float* invb = g_inv + ((size_t)bh << 10) + m0 + wr;
    float ivA[2], ivB[2];
    ivA[0] = invb[g];       ivB[0] = invb[g + 8];
    ivA[1] = invb[16 + g];  ivB[1] = invb[16 + 8 + g];

    auto issueKV = [&](int c, int st) {
        uint32_t base = sb + FST(st);
        #pragma unroll
        for (int j = 0; j < 2; j++) {
            int idx = tid + j * 256;
            int r = idx >> 3, f = idx & 7;
            size_t go = (size_t)(c * 64 + r) * Dn + f * 8;
            cpa16(base + r * 144 + f * 16,        Khg + go);
            cpa16(base + 9216 + r * 144 + f * 16, Klg + go);
        }
        #pragma unroll
        for (int j = 0; j < 2; j++) {
            int idx = tid + j * 256;
            int d = idx >> 3, f = idx & 7;
            size_t go = (size_t)d * Sn + c * 64 + f * 8;
            cpa16(base + 18432 + d * 144 + f * 16, Vhg + go);
            cpa16(base + 27648 + d * 144 + f * 16, Vlg + go);
        }
    };

    #pragma unroll
    for (int j = 0; j < 4; j++) {
        int idx = tid + j * 256;
        int r = idx >> 3, f = idx & 7;
        cpa16(sb + FQ + r * 144 + f * 16, Qg + (size_t)r * Dn + f * 8);
    }
    issueKV(0, 0);
    CP_COMMIT();

    float O[2][8][4];
    #pragma unroll
    for (int i = 0; i < 2; i++)
        #pragma unroll
        for (int j = 0; j < 8; j++)
            #pragma unroll
            for (int l = 0; l < 4; l++) O[i][j][l] = 0.f;

    for (int c = 0; c < 16; c++) {
        CP_WAIT(0);
        __syncthreads();
        if (c + 1 < 16) { issueKV(c + 1, (c + 1) & 1); CP_COMMIT(); }
        const uint32_t stg = sb + FST(c & 1);

        // process warp's 32 keys in two 16-key groups (register economy)
        #pragma unroll
        for (int kg = 0; kg < 2; kg++) {
            const int kloc = wn * 32 + kg * 16;   // key offset within 64-key chunk

            // ---- S = Q K^T for 16 keys (M32 x N16 x K64) ----
            float sa[2][2][4];
            #pragma unroll
            for (int i = 0; i < 2; i++)
                #pragma unroll
                for (int j = 0; j < 2; j++)
                    #pragma unroll
                    for (int l = 0; l < 4; l++) sa[i][j][l] = 0.f;
            #pragma unroll
            for (int ks = 0; ks < 4; ks++) {
                uint32_t qa0[4], qa1[4];
                uint32_t qo = sb + FQ + (wr + (lane & 15)) * 144 + (lane >> 4) * 16 + ks * 32;
                LDSM4(qa0, qo);
                LDSM4(qa1, qo + 16 * 144);
                uint32_t bo = (uint32_t)((kloc + (hb >> 1) * 8 + (lane & 7)) * 144
                                         + (hb & 1) * 16 + ks * 32);
                uint32_t kh4[4], kl4[4];
                LDSM4(kh4, stg + bo);
                LDSM4(kl4, stg + 9216 + bo);
                mma_f16(sa[0][0], qa0, kh4[0], kh4[1]);
                mma_f16(sa[1][0], qa1, kh4[0], kh4[1]);
                mma_f16(sa[0][1], qa0, kh4[2], kh4[3]);
                mma_f16(sa[1][1], qa1, kh4[2], kh4[3]);
                mma_f16(sa[0][0], qa0, kl4[0], kl4[1]);
                mma_f16(sa[1][0], qa1, kl4[0], kl4[1]);
                mma_f16(sa[0][1], qa0, kl4[2], kl4[3]);
                mma_f16(sa[1][1], qa1, kl4[2], kl4[3]);
            }
            // ---- normalized exp + final attn write ----
            const int cb = c * 64 + kloc;
            #pragma unroll
            for (int mt = 0; mt < 2; mt++) {
                float* r0 = attnB + (size_t)(wr + mt * 16 + g) * Sn + cb;
                float* r1 = attnB + (size_t)(wr + mt * 16 + g + 8) * Sn + cb;
                #pragma unroll
                for (int nt = 0; nt < 2; nt++) {
                    float e0 = __expf(sa[mt][nt][0] * 0.125f) * ivA[mt];
                    float e1 = __expf(sa[mt][nt][1] * 0.125f) * ivA[mt];
                    float e2 = __expf(sa[mt][nt][2] * 0.125f) * ivB[mt];
                    float e3 = __expf(sa[mt][nt][3] * 0.125f) * ivB[mt];
                    *(float2*)(r0 + nt * 8 + t * 2) = make_float2(e0, e1);
                    *(float2*)(r1 + nt * 8 + t * 2) = make_float2(e2, e3);
                    sa[mt][nt][0] = e0; sa[mt][nt][1] = e1;
                    sa[mt][nt][2] = e2; sa[mt][nt][3] = e3;
                }
            }
            // ---- repack P -> PV A-frags (16 keys = one K16 step) ----
            uint32_t PA[2][4];
            #pragma unroll
            for (int mt = 0; mt < 2; mt++) {
                PA[mt][0] = packh2(sa[mt][0][0], sa[mt][0][1]);
                PA[mt][1] = packh2(sa[mt][0][2], sa[mt][0][3]);
                PA[mt][2] = packh2(sa[mt][1][0], sa[mt][1][1]);
                PA[mt][3] = packh2(sa[mt][1][2], sa[mt][1][3]);
            }
            // ---- O += P V over these 16 keys (M32 x N64d x K16) ----
            #pragma unroll
            for (int npd = 0; npd < 4; npd++) {
                uint32_t bo = (uint32_t)((npd * 16 + (hb >> 1) * 8 + (lane & 7)) * 144
                                         + (hb & 1) * 16 + kloc * 2);
                uint32_t vh4[4], vl4[4];
                LDSM4(vh4, stg + 18432 + bo);
                LDSM4(vl4, stg + 27648 + bo);
                mma_f16(O[0][2*npd],   PA[0], vh4[0], vh4[1]);
                mma_f16(O[1][2*npd],   PA[1], vh4[0], vh4[1]);
                mma_f16(O[0][2*npd+1], PA[0], vh4[2], vh4[3]);
                mma_f16(O[1][2*npd+1], PA[1], vh4[2], vh4[3]);
                mma_f16(O[0][2*npd],   PA[0], vl4[0], vl4[1]);
                mma_f16(O[1][2*npd],   PA[1], vl4[0], vl4[1]);
                mma_f16(O[0][2*npd+1], PA[0], vl4[2], vl4[3]);
                mma_f16(O[1][2*npd+1], PA[1], vl4[2], vl4[3]);
            }
        }
    }

    // ---- merge key-half partials via smem, write ctx ----
    __syncthreads();                        // all stage reads done; reuse FST(0)
    float* red = (float*)(sm + FST(0));     // 128 rows x 64 d = 32 KB
    if (wn == 1) {
        #pragma unroll
        for (int mt = 0; mt < 2; mt++)
            #pragma unroll
            for (int nt = 0; nt < 8; nt++) {
                int b0 = (wr + mt * 16 + g) * 64 + nt * 8 + t * 2;
                int b1 = (wr + mt * 16 + g + 8) * 64 + nt * 8 + t * 2;
                *(float2*)(red + b0) = make_float2(O[mt][nt][0], O[mt][nt][1]);
                *(float2*)(red + b1) = make_float2(O[mt][nt][2], O[mt][nt][3]);
            }
    }
    __syncthreads();
    if (wn == 0) {
        const int bb = bh >> 4, h = bh & 15;
        #pragma unroll
        for (int mt = 0; mt < 2; mt++) {
            int m = m0 + wr + mt * 16 + g;
            __half* c0 = g_ctx + ((size_t)(bb * Sn + m)) * En + h * Dn;
            __half* c1 = g_ctx + ((size_t)(bb * Sn + m + 8)) * En + h * Dn;
            #pragma unroll
            for (int nt = 0; nt < 8; nt++) {
                int b0 = (wr + mt * 16 + g) * 64 + nt * 8 + t * 2;
                int b1 = (wr + mt * 16 + g + 8) * 64 + nt * 8 + t * 2;
                float2 p0 = *(float2*)(red + b0);
                float2 p1 = *(float2*)(red + b1);
                int d = nt * 8 + t * 2;
                *(uint32_t*)(c0 + d) = packh2(O[mt][nt][0] + p0.x, O[mt][nt][1] + p0.y);
                *(uint32_t*)(c1 + d) = packh2(O[mt][nt][2] + p1.x, O[mt][nt][3] + p1.y);
            }
        }
    }
}

// ---------------------------------------------------------------------------
// Kernel: output projection. grid (8, 64)
// ---------------------------------------------------------------------------
__global__ void __launch_bounds__(256, 2) outproj_kernel(
    const float* __restrict__ ob, float* __restrict__ Out)
{
    const int tid = threadIdx.x;
    const int m0 = blockIdx.y * 128, n0 = blockIdx.x * 128;
    const __half* A  = g_ctx + (size_t)m0 * 1024;
    const __half* Bh = g_wh + (size_t)3 * W_ELEMS + (size_t)n0 * 1024;
    const __half* Bl = g_wl + (size_t)3 * W_ELEMS + (size_t)n0 * 1024;

    gemm128(A, Bh, Bl, tid,
        [&](float acc[4][4][4], int wm, int wn, int lane) {
            const int g = lane >> 2, t = lane & 3;
            #pragma unroll
            for (int mt = 0; mt < 4; mt++) {
                int m = m0 + wm * 64 + mt * 16 + g;
                float* orow = Out + (size_t)m * En;
                #pragma unroll
                for (int nt = 0; nt < 4; nt++) {
                    int n = n0 + wn * 32 + nt * 8 + t * 2;
                    float2 bv = *(const float2*)(ob + n);
                    *(float2*)(orow + n) =
                        make_float2(acc[mt][nt][0] + bv.x, acc[mt][nt][1] + bv.y);
                    *(float2*)(orow + 8 * En + n) =
                        make_float2(acc[mt][nt][2] + bv.x, acc[mt][nt][3] + bv.y);
                }
            }
        });
}

// ---------------------------------------------------------------------------
extern "C" void kernel_launch(void* const* d_in, const int* in_sizes, int n_in,
                              void* d_out, int out_size)
{
    const float* q_in  = (const float*)d_in[0];
    const float* k_in  = (const float*)d_in[1];
    const float* v_in  = (const float*)d_in[2];
    const float* q_w   = (const float*)d_in[3];
    const float* q_b   = (const float*)d_in[4];
    const float* k_w   = (const float*)d_in[5];
    const float* k_b   = (const float*)d_in[6];
    const float* v_w   = (const float*)d_in[7];
    const float* v_b   = (const float*)d_in[8];
    const float* out_w = (const float*)d_in[9];
    const float* out_b = (const float*)d_in[10];

    float* out  = (float*)d_out;
    float* attn = out;                  // (B,H,S,S)
    float* outp = out + ATTN_ELEMS;     // (B,S,E)

    cudaFuncSetAttribute(proj_kernel,       cudaFuncAttributeMaxDynamicSharedMemorySize, GEMM_SMEM);
    cudaFuncSetAttribute(sum_kernel,        cudaFuncAttributeMaxDynamicSharedMemorySize, SUM_SMEM);
    cudaFuncSetAttribute(fused_attn_kernel, cudaFuncAttributeMaxDynamicSharedMemorySize, FUSED_SMEM);
    cudaFuncSetAttribute(outproj_kernel,    cudaFuncAttributeMaxDynamicSharedMemorySize, GEMM_SMEM);

    split_kernel<<<dim3(8192, 7), 256>>>(q_in, k_in, v_in, q_w, k_w, v_w, out_w);
    proj_kernel<<<dim3(8, 64, 3), 256, GEMM_SMEM>>>(q_b, k_b, v_b);
    sum_kernel<<<dim3(8, 128), 256, SUM_SMEM>>>();
    fused_attn_kernel<<<dim3(8, 128), 256, FUSED_SMEM>>>(attn);
    outproj_kernel<<<dim3(8, 64), 256, GEMM_SMEM>>>(out_b, outp);
}

// round 12
// speedup vs baseline: 1.1571x; 1.1315x over previous
#include <cuda_runtime.h>
#include <cuda_fp16.h>
#include <cstdint>

#define Bn 8
#define Sn 1024
#define En 1024
#define Hn 16
#define Dn 64
#define ATTN_ELEMS ((size_t)Bn*Hn*Sn*Sn)
#define IN_ELEMS (Bn*Sn*En)     // 8388608
#define W_ELEMS  (En*En)        // 1048576

// fp16 operand storage (allocation-free rule: __device__ globals)
__device__ __half g_x[3*IN_ELEMS];                     // inputs q,k,v (single)
__device__ __half g_wh[4*W_ELEMS], g_wl[4*W_ELEMS];    // weights hi/lo
__device__ __half g_q[IN_ELEMS];                       // (b,h,s,d) single
__device__ __half g_k[IN_ELEMS];                       // (b,h,s,d) single
__device__ __half g_vt[IN_ELEMS];                      // (b,h,d,s) single, transposed
__device__ __half g_ctx[IN_ELEMS];                     // (b,s,e) single
__device__ float g_inv[Bn*Hn*Sn];                      // softmax 1/rowsum

// ---------------- PTX primitives ----------------
__device__ __forceinline__ uint32_t smem_u32(const void* p) {
    uint32_t a;
    asm("{ .reg .u64 t; cvta.to.shared.u64 t, %1; cvt.u32.u64 %0, t; }" : "=r"(a) : "l"(p));
    return a;
}
__device__ __forceinline__ void cpa16(uint32_t sdst, const void* gsrc) {
    asm volatile("cp.async.cg.shared.global [%0], [%1], 16;" :: "r"(sdst), "l"(gsrc));
}
#define CP_COMMIT() asm volatile("cp.async.commit_group;" ::: "memory")
#define CP_WAIT(N)  asm volatile("cp.async.wait_group %0;" :: "n"(N) : "memory")

#define LDSM4(R, A) asm volatile("ldmatrix.sync.aligned.m8n8.x4.shared.b16 {%0,%1,%2,%3}, [%4];" \
    : "=r"((R)[0]), "=r"((R)[1]), "=r"((R)[2]), "=r"((R)[3]) : "r"(A))

__device__ __forceinline__ void mma_f16(float c[4], const uint32_t a[4],
                                        uint32_t b0, uint32_t b1) {
    asm volatile(
        "mma.sync.aligned.m16n8k16.row.col.f32.f16.f16.f32 "
        "{%0,%1,%2,%3}, {%4,%5,%6,%7}, {%8,%9}, {%0,%1,%2,%3};"
        : "+f"(c[0]), "+f"(c[1]), "+f"(c[2]), "+f"(c[3])
        : "r"(a[0]), "r"(a[1]), "r"(a[2]), "r"(a[3]), "r"(b0), "r"(b1));
}

__device__ __forceinline__ uint32_t packh2(float a, float b) {
    __half2 h = __floats2half2_rn(a, b);
    return *(uint32_t*)&h;
}
__device__ __forceinline__ void split1(float x, __half& hi, __half& lo) {
    hi = __float2half_rn(x);
    lo = __float2half_rn(x - __half2float(hi));
}

// ---------------------------------------------------------------------------
// split_kernel: inputs -> fp16 single; weights -> fp16 hi/lo. grid (8192, 7)
// ---------------------------------------------------------------------------
__global__ void __launch_bounds__(256) split_kernel(
    const float* __restrict__ xq, const float* __restrict__ xk, const float* __restrict__ xv,
    const float* __restrict__ wq, const float* __restrict__ wk,
    const float* __restrict__ wv, const float* __restrict__ wo)
{
    const int z = blockIdx.y;
    int i = blockIdx.x * 256 + threadIdx.x;
    if (z < 3) {
        if (i >= IN_ELEMS / 4) return;
        const float* src = (z == 0) ? xq : ((z == 1) ? xk : xv);
        float4 v = ((const float4*)src)[i];
        uint2 o;
        o.x = packh2(v.x, v.y); o.y = packh2(v.z, v.w);
        ((uint2*)(g_x + (size_t)z * IN_ELEMS))[i] = o;
    } else {
        if (i >= W_ELEMS / 4) return;
        const float* src = (z == 3) ? wq : ((z == 4) ? wk : ((z == 5) ? wv : wo));
        float4 v = ((const float4*)src)[i];
        __half h0, l0, h1, l1, h2, l2, h3, l3;
        split1(v.x, h0, l0); split1(v.y, h1, l1);
        split1(v.z, h2, l2); split1(v.w, h3, l3);
        uint2 hi, lo;
        hi.x = packh2(__half2float(h0), __half2float(h1));
        hi.y = packh2(__half2float(h2), __half2float(h3));
        lo.x = packh2(__half2float(l0), __half2float(l1));
        lo.y = packh2(__half2float(l2), __half2float(l3));
        ((uint2*)(g_wh + (size_t)(z - 3) * W_ELEMS))[i] = hi;
        ((uint2*)(g_wl + (size_t)(z - 3) * W_ELEMS))[i] = lo;
    }
}

// ---------------------------------------------------------------------------
// 2-term warp MMA on a K=32 chunk (A single, B hi/lo), stride 80.
// Warp tile 64 rows x 32 cols. R9 instruction order (measured best).
// ---------------------------------------------------------------------------
__device__ __forceinline__ void chunk2(uint32_t A, uint32_t Bh, uint32_t Bl,
                                       int arow, int bcol, int lane,
                                       float acc[4][4][4]) {
    const int hb = (lane >> 3) & 3;
    const uint32_t abase = (uint32_t)((arow + (lane & 15)) * 80 + (lane >> 4) * 16);
    const uint32_t bbase = (uint32_t)((bcol + (hb >> 1) * 8 + (lane & 7)) * 80 + (hb & 1) * 16);
    #pragma unroll
    for (int ks = 0; ks < 2; ks++) {
        uint32_t a[4][4];
        #pragma unroll
        for (int mt = 0; mt < 4; mt++)
            LDSM4(a[mt], A + abase + mt * 16 * 80 + ks * 32);
        #pragma unroll
        for (int np = 0; np < 2; np++) {
            uint32_t bh4[4], bl4[4];
            LDSM4(bh4, Bh + bbase + np * 16 * 80 + ks * 32);
            LDSM4(bl4, Bl + bbase + np * 16 * 80 + ks * 32);
            #pragma unroll
            for (int mt = 0; mt < 4; mt++) {
                mma_f16(acc[mt][2*np],   a[mt], bh4[0], bh4[1]);
                mma_f16(acc[mt][2*np],   a[mt], bl4[0], bl4[1]);
                mma_f16(acc[mt][2*np+1], a[mt], bh4[2], bh4[3]);
                mma_f16(acc[mt][2*np+1], a[mt], bl4[2], bl4[3]);
            }
        }
    }
}

// ---------------------------------------------------------------------------
// 128x128 GEMM, K=1024, 2-stage cp.async, single sync per chunk.
// ---------------------------------------------------------------------------
#define PSTG 30720
#define GEMM_SMEM (2*PSTG)

__device__ __forceinline__ void gissue(uint32_t sbase,
    const __half* A, const __half* Bh, const __half* Bl, int tid)
{
    #pragma unroll 2
    for (int idx = tid; idx < 512; idx += 256) {
        int r = idx >> 2, f = idx & 3;
        uint32_t so = (uint32_t)(r * 80 + f * 16);
        size_t go = (size_t)r * 1024 + f * 8;
        cpa16(sbase + so,         A + go);
        cpa16(sbase + 10240 + so, Bh + go);
        cpa16(sbase + 20480 + so, Bl + go);
    }
}

template<typename EPI>
__device__ __forceinline__ void gemm128(
    const __half* A, const __half* Bh, const __half* Bl, int tid, EPI epi)
{
    extern __shared__ char sm[];
    const uint32_t sb = smem_u32(sm);
    const int lane = tid & 31, wid = tid >> 5;
    const int wm = wid & 1, wn = wid >> 1;   // 2 x 4 warp grid

    float acc[4][4][4];
    #pragma unroll
    for (int i = 0; i < 4; i++)
        #pragma unroll
        for (int j = 0; j < 4; j++)
            #pragma unroll
            for (int l = 0; l < 4; l++) acc[i][j][l] = 0.f;

    gissue(sb, A, Bh, Bl, tid);
    CP_COMMIT();
    for (int c = 0; c < 32; c++) {
        CP_WAIT(0);
        __syncthreads();
        if (c + 1 < 32) {
            gissue(sb + ((c + 1) & 1) * PSTG,
                   A + (c + 1) * 32, Bh + (c + 1) * 32, Bl + (c + 1) * 32, tid);
            CP_COMMIT();
        }
        uint32_t s = sb + (c & 1) * PSTG;
        chunk2(s, s + 10240, s + 20480, wm * 64, wn * 32, lane, acc);
    }
    epi(acc, wm, wn, lane);
}

// ---------------------------------------------------------------------------
// Kernel: QKV projections. grid (8, 64, 3). Q/K/V all stored single fp16.
// ---------------------------------------------------------------------------
__global__ void __launch_bounds__(256, 2) proj_kernel(
    const float* __restrict__ qb, const float* __restrict__ kb, const float* __restrict__ vb)
{
    const int z = blockIdx.z;
    const int tid = threadIdx.x;
    const int m0 = blockIdx.y * 128, n0 = blockIdx.x * 128;
    const __half* A  = g_x  + (size_t)z * IN_ELEMS + (size_t)m0 * 1024;
    const __half* Bh = g_wh + (size_t)z * W_ELEMS + (size_t)n0 * 1024;
    const __half* Bl = g_wl + (size_t)z * W_ELEMS + (size_t)n0 * 1024;
    const float* bias = (z == 0) ? qb : ((z == 1) ? kb : vb);

    gemm128(A, Bh, Bl, tid,
        [&](float acc[4][4][4], int wm, int wn, int lane) {
            const int g = lane >> 2, t = lane & 3;
            #pragma unroll
            for (int mt = 0; mt < 4; mt++) {
                int m = m0 + wm * 64 + mt * 16 + g;
                int bb = m >> 10, s = m & 1023;
                #pragma unroll
                for (int nt = 0; nt < 4; nt++) {
                    int n = n0 + wn * 32 + nt * 8 + t * 2;
                    int h = n >> 6, d = n & 63;
                    float2 bv = *(const float2*)(bias + n);
                    float c0 = acc[mt][nt][0] + bv.x, c1 = acc[mt][nt][1] + bv.y;
                    float c2 = acc[mt][nt][2] + bv.x, c3 = acc[mt][nt][3] + bv.y;
                    if (z < 2) {
                        __half* dst = (z == 0) ? g_q : g_k;
                        size_t a0 = (((size_t)bb * Hn + h) * Sn + s) * Dn + d;
                        *(uint32_t*)(dst + a0)          = packh2(c0, c1);
                        *(uint32_t*)(dst + a0 + 8 * Dn) = packh2(c2, c3);
                    } else {
                        // V transposed (b,h,d,s), single fp16
                        size_t a0 = (((size_t)bb * Hn + h) * Dn + d) * Sn + s;
                        g_vt[a0]          = __float2half_rn(c0);
                        g_vt[a0 + Sn]     = __float2half_rn(c1);
                        g_vt[a0 + 8]      = __float2half_rn(c2);
                        g_vt[a0 + Sn + 8] = __float2half_rn(c3);
                    }
                }
            }
        });
}

// ---------------------------------------------------------------------------
// Pass 1: softmax row sums (single fp16 scores — identical math to pass 2,
// so normalization is exact). grid (8, 128)
// ---------------------------------------------------------------------------
#define SQ 0
#define SKH(st) (18432 + (st)*9216)
#define SSUM 36864
#define SUM_SMEM 37376

__global__ void __launch_bounds__(256, 2) sum_kernel()
{
    extern __shared__ char sm[];
    const uint32_t sb = smem_u32(sm);
    float* sums = (float*)(sm + SSUM);

    const int tid = threadIdx.x, lane = tid & 31, w = tid >> 5;
    const int g = lane >> 2, t = lane & 3;
    const int wr = w * 16;
    const int hb = (lane >> 3) & 3;
    const int m0 = blockIdx.x * 128;
    const int bh = blockIdx.y;

    const __half* Qg  = g_q + ((size_t)bh * Sn + m0) * Dn;
    const __half* Khg = g_k + (size_t)bh * Sn * Dn;

    auto issueK = [&](int c, int st) {
        uint32_t base = sb + SKH(st);
        #pragma unroll
        for (int j = 0; j < 2; j++) {
            int idx = tid + j * 256;
            int r = idx >> 3, f = idx & 7;
            cpa16(base + r * 144 + f * 16, Khg + (size_t)(c * 64 + r) * Dn + f * 8);
        }
    };

    #pragma unroll
    for (int j = 0; j < 4; j++) {
        int idx = tid + j * 256;
        int r = idx >> 3, f = idx & 7;
        cpa16(sb + SQ + r * 144 + f * 16, Qg + (size_t)r * Dn + f * 8);
    }
    issueK(0, 0);
    CP_COMMIT();

    float rs0 = 0.f, rs1 = 0.f;
    for (int c = 0; c < 16; c++) {
        CP_WAIT(0);
        __syncthreads();
        if (c + 1 < 16) { issueK(c + 1, (c + 1) & 1); CP_COMMIT(); }
        const uint32_t stg = sb + SKH(c & 1);

        float sa[8][4];
        #pragma unroll
        for (int i = 0; i < 8; i++)
            #pragma unroll
            for (int l = 0; l < 4; l++) sa[i][l] = 0.f;
        #pragma unroll
        for (int ks = 0; ks < 4; ks++) {
            uint32_t qa[4];
            LDSM4(qa, sb + SQ + (wr + (lane & 15)) * 144 + (lane >> 4) * 16 + ks * 32);
            #pragma unroll
            for (int np = 0; np < 4; np++) {
                uint32_t bo = (uint32_t)((np * 16 + (hb >> 1) * 8 + (lane & 7)) * 144
                                         + (hb & 1) * 16 + ks * 32);
                uint32_t kh4[4];
                LDSM4(kh4, stg + bo);
                mma_f16(sa[2*np],   qa, kh4[0], kh4[1]);
                mma_f16(sa[2*np+1], qa, kh4[2], kh4[3]);
            }
        }
        #pragma unroll
        for (int j = 0; j < 8; j++) {
            rs0 += __expf(sa[j][0] * 0.125f) + __expf(sa[j][1] * 0.125f);
            rs1 += __expf(sa[j][2] * 0.125f) + __expf(sa[j][3] * 0.125f);
        }
    }

    rs0 += __shfl_xor_sync(0xffffffffu, rs0, 1);
    rs0 += __shfl_xor_sync(0xffffffffu, rs0, 2);
    rs1 += __shfl_xor_sync(0xffffffffu, rs1, 1);
    rs1 += __shfl_xor_sync(0xffffffffu, rs1, 2);
    if (t == 0) { sums[wr + g] = rs0; sums[wr + g + 8] = rs1; }
    __syncthreads();
    if (tid < 128)
        g_inv[((size_t)bh << 10) + m0 + tid] = 1.0f / sums[tid];
}

// ---------------------------------------------------------------------------
// Pass 2: fused attention, K and V single fp16 (MMA count halved vs R11).
// Warp grid 4m x 2n; each warp's 32 keys in two 16-key groups.
// smem: Q@0 (18432) | stage st @ 18432+st*18432: KH+0 (9216) VH+9216 (9216)
//       O-merge reuses stage area (36864 >= 32768). Total 55296.
// ---------------------------------------------------------------------------
#define FQ 0
#define FST(st) (18432 + (st)*18432)
#define FUSED_SMEM 55296

__global__ void __launch_bounds__(256, 2) fused_attn_kernel(float* __restrict__ attn)
{
    extern __shared__ char sm[];
    const uint32_t sb = smem_u32(sm);

    const int tid = threadIdx.x, lane = tid & 31, w = tid >> 5;
    const int g = lane >> 2, t = lane & 3;
    const int wm = w & 3, wn = w >> 2;      // 4 m-warps x 2 n-warps
    const int wr = wm * 32;
    const int hb = (lane >> 3) & 3;
    const int m0 = blockIdx.x * 128;
    const int bh = blockIdx.y;

    const __half* Qg  = g_q  + ((size_t)bh * Sn + m0) * Dn;
    const __half* Khg = g_k  + (size_t)bh * Sn * Dn;
    const __half* Vhg = g_vt + (size_t)bh * Dn * Sn;
    float* attnB = attn + ((size_t)bh * Sn + m0) * Sn;

    const float* invb = g_inv + ((size_t)bh << 10) + m0 + wr;
    float ivA[2], ivB[2];
    ivA[0] = invb[g];       ivB[0] = invb[g + 8];
    ivA[1] = invb[16 + g];  ivB[1] = invb[16 + 8 + g];

    auto issueKV = [&](int c, int st) {
        uint32_t base = sb + FST(st);
        #pragma unroll
        for (int j = 0; j < 2; j++) {
            int idx = tid + j * 256;
            int r = idx >> 3, f = idx & 7;
            cpa16(base + r * 144 + f * 16, Khg + (size_t)(c * 64 + r) * Dn + f * 8);
        }
        #pragma unroll
        for (int j = 0; j < 2; j++) {
            int idx = tid + j * 256;
            int d = idx >> 3, f = idx & 7;
            cpa16(base + 9216 + d * 144 + f * 16, Vhg + (size_t)d * Sn + c * 64 + f * 8);
        }
    };

    #pragma unroll
    for (int j = 0; j < 4; j++) {
        int idx = tid + j * 256;
        int r = idx >> 3, f = idx & 7;
        cpa16(sb + FQ + r * 144 + f * 16, Qg + (size_t)r * Dn + f * 8);
    }
    issueKV(0, 0);
    CP_COMMIT();

    float O[2][8][4];
    #pragma unroll
    for (int i = 0; i < 2; i++)
        #pragma unroll
        for (int j = 0; j < 8; j++)
            #pragma unroll
            for (int l = 0; l < 4; l++) O[i][j][l] = 0.f;

    for (int c = 0; c < 16; c++) {
        CP_WAIT(0);
        __syncthreads();
        if (c + 1 < 16) { issueKV(c + 1, (c + 1) & 1); CP_COMMIT(); }
        const uint32_t stg = sb + FST(c & 1);

        #pragma unroll
        for (int kg = 0; kg < 2; kg++) {
            const int kloc = wn * 32 + kg * 16;

            // ---- S = Q K^T for 16 keys (M32 x N16 x K64), single K ----
            float sa[2][2][4];
            #pragma unroll
            for (int i = 0; i < 2; i++)
                #pragma unroll
                for (int j = 0; j < 2; j++)
                    #pragma unroll
                    for (int l = 0; l < 4; l++) sa[i][j][l] = 0.f;
            #pragma unroll
            for (int ks = 0; ks < 4; ks++) {
                uint32_t qa0[4], qa1[4];
                uint32_t qo = sb + FQ + (wr + (lane & 15)) * 144 + (lane >> 4) * 16 + ks * 32;
                LDSM4(qa0, qo);
                LDSM4(qa1, qo + 16 * 144);
                uint32_t bo = (uint32_t)((kloc + (hb >> 1) * 8 + (lane & 7)) * 144
                                         + (hb & 1) * 16 + ks * 32);
                uint32_t kh4[4];
                LDSM4(kh4, stg + bo);
                mma_f16(sa[0][0], qa0, kh4[0], kh4[1]);
                mma_f16(sa[1][0], qa1, kh4[0], kh4[1]);
                mma_f16(sa[0][1], qa0, kh4[2], kh4[3]);
                mma_f16(sa[1][1], qa1, kh4[2], kh4[3]);
            }
            // ---- normalized exp + final attn write ----
            const int cb = c * 64 + kloc;
            #pragma unroll
            for (int mt = 0; mt < 2; mt++) {
                float* r0 = attnB + (size_t)(wr + mt * 16 + g) * Sn + cb;
                float* r1 = attnB + (size_t)(wr + mt * 16 + g + 8) * Sn + cb;
                #pragma unroll
                for (int nt = 0; nt < 2; nt++) {
                    float e0 = __expf(sa[mt][nt][0] * 0.125f) * ivA[mt];
                    float e1 = __expf(sa[mt][nt][1] * 0.125f) * ivA[mt];
                    float e2 = __expf(sa[mt][nt][2] * 0.125f) * ivB[mt];
                    float e3 = __expf(sa[mt][nt][3] * 0.125f) * ivB[mt];
                    *(float2*)(r0 + nt * 8 + t * 2) = make_float2(e0, e1);
                    *(float2*)(r1 + nt * 8 + t * 2) = make_float2(e2, e3);
                    sa[mt][nt][0] = e0; sa[mt][nt][1] = e1;
                    sa[mt][nt][2] = e2; sa[mt][nt][3] = e3;
                }
            }
            // ---- repack P -> PV A-frags (one K16 step) ----
            uint32_t PA[2][4];
            #pragma unroll
            for (int mt = 0; mt < 2; mt++) {
                PA[mt][0] = packh2(sa[mt][0][0], sa[mt][0][1]);
                PA[mt][1] = packh2(sa[mt][0][2], sa[mt][0][3]);
                PA[mt][2] = packh2(sa[mt][1][0], sa[mt][1][1]);
                PA[mt][3] = packh2(sa[mt][1][2], sa[mt][1][3]);
            }
            // ---- O += P V over these 16 keys (single V) ----
            #pragma unroll
            for (int npd = 0; npd < 4; npd++) {
                uint32_t bo = (uint32_t)((npd * 16 + (hb >> 1) * 8 + (lane & 7)) * 144
                                         + (hb & 1) * 16 + kloc * 2);
                uint32_t vh4[4];
                LDSM4(vh4, stg + 9216 + bo);
                mma_f16(O[0][2*npd],   PA[0], vh4[0], vh4[1]);
                mma_f16(O[1][2*npd],   PA[1], vh4[0], vh4[1]);
                mma_f16(O[0][2*npd+1], PA[0], vh4[2], vh4[3]);
                mma_f16(O[1][2*npd+1], PA[1], vh4[2], vh4[3]);
            }
        }
    }

    // ---- merge key-half partials via smem, write ctx ----
    __syncthreads();                        // all stage reads done; reuse FST(0)
    float* red = (float*)(sm + FST(0));     // 128 rows x 64 d = 32 KB
    if (wn == 1) {
        #pragma unroll
        for (int mt = 0; mt < 2; mt++)
            #pragma unroll
            for (int nt = 0; nt < 8; nt++) {
                int b0 = (wr + mt * 16 + g) * 64 + nt * 8 + t * 2;
                int b1 = (wr + mt * 16 + g + 8) * 64 + nt * 8 + t * 2;
                *(float2*)(red + b0) = make_float2(O[mt][nt][0], O[mt][nt][1]);
                *(float2*)(red + b1) = make_float2(O[mt][nt][2], O[mt][nt][3]);
            }
    }
    __syncthreads();
    if (wn == 0) {
        const int bb = bh >> 4, h = bh & 15;
        #pragma unroll
        for (int mt = 0; mt < 2; mt++) {
            int m = m0 + wr + mt * 16 + g;
            __half* c0 = g_ctx + ((size_t)(bb * Sn + m)) * En + h * Dn;
            __half* c1 = g_ctx + ((size_t)(bb * Sn + m + 8)) * En + h * Dn;
            #pragma unroll
            for (int nt = 0; nt < 8; nt++) {
                int b0 = (wr + mt * 16 + g) * 64 + nt * 8 + t * 2;
                int b1 = (wr + mt * 16 + g + 8) * 64 + nt * 8 + t * 2;
                float2 p0 = *(float2*)(red + b0);
                float2 p1 = *(float2*)(red + b1);
                int d = nt * 8 + t * 2;
                *(uint32_t*)(c0 + d) = packh2(O[mt][nt][0] + p0.x, O[mt][nt][1] + p0.y);
                *(uint32_t*)(c1 + d) = packh2(O[mt][nt][2] + p1.x, O[mt][nt][3] + p1.y);
            }
        }
    }
}

// ---------------------------------------------------------------------------
// Kernel: output projection. grid (8, 64)
// ---------------------------------------------------------------------------
__global__ void __launch_bounds__(256, 2) outproj_kernel(
    const float* __restrict__ ob, float* __restrict__ Out)
{
    const int tid = threadIdx.x;
    const int m0 = blockIdx.y * 128, n0 = blockIdx.x * 128;
    const __half* A  = g_ctx + (size_t)m0 * 1024;
    const __half* Bh = g_wh + (size_t)3 * W_ELEMS + (size_t)n0 * 1024;
    const __half* Bl = g_wl + (size_t)3 * W_ELEMS + (size_t)n0 * 1024;

    gemm128(A, Bh, Bl, tid,
        [&](float acc[4][4][4], int wm, int wn, int lane) {
            const int g = lane >> 2, t = lane & 3;
            #pragma unroll
            for (int mt = 0; mt < 4; mt++) {
                int m = m0 + wm * 64 + mt * 16 + g;
                float* orow = Out + (size_t)m * En;
                #pragma unroll
                for (int nt = 0; nt < 4; nt++) {
                    int n = n0 + wn * 32 + nt * 8 + t * 2;
                    float2 bv = *(const float2*)(ob + n);
                    *(float2*)(orow + n) =
                        make_float2(acc[mt][nt][0] + bv.x, acc[mt][nt][1] + bv.y);
                    *(float2*)(orow + 8 * En + n) =
                        make_float2(acc[mt][nt][2] + bv.x, acc[mt][nt][3] + bv.y);
                }
            }
        });
}

// ---------------------------------------------------------------------------
extern "C" void kernel_launch(void* const* d_in, const int* in_sizes, int n_in,
                              void* d_out, int out_size)
{
    const float* q_in  = (const float*)d_in[0];
    const float* k_in  = (const float*)d_in[1];
    const float* v_in  = (const float*)d_in[2];
    const float* q_w   = (const float*)d_in[3];
    const float* q_b   = (const float*)d_in[4];
    const float* k_w   = (const float*)d_in[5];
    const float* k_b   = (const float*)d_in[6];
    const float* v_w   = (const float*)d_in[7];
    const float* v_b   = (const float*)d_in[8];
    const float* out_w = (const float*)d_in[9];
    const float* out_b = (const float*)d_in[10];

    float* out  = (float*)d_out;
    float* attn = out;                  // (B,H,S,S)
    float* outp = out + ATTN_ELEMS;     // (B,S,E)

    cudaFuncSetAttribute(proj_kernel,       cudaFuncAttributeMaxDynamicSharedMemorySize, GEMM_SMEM);
    cudaFuncSetAttribute(sum_kernel,        cudaFuncAttributeMaxDynamicSharedMemorySize, SUM_SMEM);
    cudaFuncSetAttribute(fused_attn_kernel, cudaFuncAttributeMaxDynamicSharedMemorySize, FUSED_SMEM);
    cudaFuncSetAttribute(outproj_kernel,    cudaFuncAttributeMaxDynamicSharedMemorySize, GEMM_SMEM);

    split_kernel<<<dim3(8192, 7), 256>>>(q_in, k_in, v_in, q_w, k_w, v_w, out_w);
    proj_kernel<<<dim3(8, 64, 3), 256, GEMM_SMEM>>>(q_b, k_b, v_b);
    sum_kernel<<<dim3(8, 128), 256, SUM_SMEM>>>();
    fused_attn_kernel<<<dim3(8, 128), 256, FUSED_SMEM>>>(attn);
    outproj_kernel<<<dim3(8, 64), 256, GEMM_SMEM>>>(out_b, outp);
}

// round 13
// speedup vs baseline: 1.3258x; 1.1458x over previous
#include <cuda_runtime.h>
#include <cuda_fp16.h>
#include <cstdint>

#define Bn 8
#define Sn 1024
#define En 1024
#define Hn 16
#define Dn 64
#define ATTN_ELEMS ((size_t)Bn*Hn*Sn*Sn)
#define IN_ELEMS (Bn*Sn*En)     // 8388608
#define W_ELEMS  (En*En)        // 1048576

// fp16 operand storage (allocation-free rule: __device__ globals)
__device__ __half g_x[3*IN_ELEMS];                     // inputs q,k,v (single)
__device__ __half g_wh[4*W_ELEMS], g_wl[4*W_ELEMS];    // weights hi (+lo for q,k)
__device__ __half g_q[IN_ELEMS];                       // (b,h,s,d) single
__device__ __half g_k[IN_ELEMS];                       // (b,h,s,d) single
__device__ __half g_vt[IN_ELEMS];                      // (b,h,d,s) single, transposed
__device__ __half g_ctx[IN_ELEMS];                     // (b,s,e) single
__device__ float g_inv[Bn*Hn*Sn];                      // softmax 1/rowsum

// ---------------- PTX primitives ----------------
__device__ __forceinline__ uint32_t smem_u32(const void* p) {
    uint32_t a;
    asm("{ .reg .u64 t; cvta.to.shared.u64 t, %1; cvt.u32.u64 %0, t; }" : "=r"(a) : "l"(p));
    return a;
}
__device__ __forceinline__ void cpa16(uint32_t sdst, const void* gsrc) {
    asm volatile("cp.async.cg.shared.global [%0], [%1], 16;" :: "r"(sdst), "l"(gsrc));
}
#define CP_COMMIT() asm volatile("cp.async.commit_group;" ::: "memory")
#define CP_WAIT(N)  asm volatile("cp.async.wait_group %0;" :: "n"(N) : "memory")

#define LDSM4(R, A) asm volatile("ldmatrix.sync.aligned.m8n8.x4.shared.b16 {%0,%1,%2,%3}, [%4];" \
    : "=r"((R)[0]), "=r"((R)[1]), "=r"((R)[2]), "=r"((R)[3]) : "r"(A))

__device__ __forceinline__ void mma_f16(float c[4], const uint32_t a[4],
                                        uint32_t b0, uint32_t b1) {
    asm volatile(
        "mma.sync.aligned.m16n8k16.row.col.f32.f16.f16.f32 "
        "{%0,%1,%2,%3}, {%4,%5,%6,%7}, {%8,%9}, {%0,%1,%2,%3};"
        : "+f"(c[0]), "+f"(c[1]), "+f"(c[2]), "+f"(c[3])
        : "r"(a[0]), "r"(a[1]), "r"(a[2]), "r"(a[3]), "r"(b0), "r"(b1));
}

__device__ __forceinline__ uint32_t packh2(float a, float b) {
    __half2 h = __floats2half2_rn(a, b);
    return *(uint32_t*)&h;
}
__device__ __forceinline__ void split1(float x, __half& hi, __half& lo) {
    hi = __float2half_rn(x);
    lo = __float2half_rn(x - __half2float(hi));
}

// ---------------------------------------------------------------------------
// split_kernel: inputs -> fp16 single; weights -> fp16 hi/lo. grid (8192, 7)
// (lo written for all weights; only q,k GEMMs consume it)
// ---------------------------------------------------------------------------
__global__ void __launch_bounds__(256) split_kernel(
    const float* __restrict__ xq, const float* __restrict__ xk, const float* __restrict__ xv,
    const float* __restrict__ wq, const float* __restrict__ wk,
    const float* __restrict__ wv, const float* __restrict__ wo)
{
    const int z = blockIdx.y;
    int i = blockIdx.x * 256 + threadIdx.x;
    if (z < 3) {
        if (i >= IN_ELEMS / 4) return;
        const float* src = (z == 0) ? xq : ((z == 1) ? xk : xv);
        float4 v = ((const float4*)src)[i];
        uint2 o;
        o.x = packh2(v.x, v.y); o.y = packh2(v.z, v.w);
        ((uint2*)(g_x + (size_t)z * IN_ELEMS))[i] = o;
    } else {
        if (i >= W_ELEMS / 4) return;
        const float* src = (z == 3) ? wq : ((z == 4) ? wk : ((z == 5) ? wv : wo));
        float4 v = ((const float4*)src)[i];
        __half h0, l0, h1, l1, h2, l2, h3, l3;
        split1(v.x, h0, l0); split1(v.y, h1, l1);
        split1(v.z, h2, l2); split1(v.w, h3, l3);
        uint2 hi, lo;
        hi.x = packh2(__half2float(h0), __half2float(h1));
        hi.y = packh2(__half2float(h2), __half2float(h3));
        lo.x = packh2(__half2float(l0), __half2float(l1));
        lo.y = packh2(__half2float(l2), __half2float(l3));
        ((uint2*)(g_wh + (size_t)(z - 3) * W_ELEMS))[i] = hi;
        ((uint2*)(g_wl + (size_t)(z - 3) * W_ELEMS))[i] = lo;
    }
}

// ---------------------------------------------------------------------------
// Warp MMA on a K=32 chunk, warp tile 64 rows x 32 cols, stride 80.
// chunk2: B hi+lo (2-term); chunk1: B single.
// ---------------------------------------------------------------------------
__device__ __forceinline__ void chunk2(uint32_t A, uint32_t Bh, uint32_t Bl,
                                       int arow, int bcol, int lane,
                                       float acc[4][4][4]) {
    const int hb = (lane >> 3) & 3;
    const uint32_t abase = (uint32_t)((arow + (lane & 15)) * 80 + (lane >> 4) * 16);
    const uint32_t bbase = (uint32_t)((bcol + (hb >> 1) * 8 + (lane & 7)) * 80 + (hb & 1) * 16);
    #pragma unroll
    for (int ks = 0; ks < 2; ks++) {
        uint32_t a[4][4];
        #pragma unroll
        for (int mt = 0; mt < 4; mt++)
            LDSM4(a[mt], A + abase + mt * 16 * 80 + ks * 32);
        #pragma unroll
        for (int np = 0; np < 2; np++) {
            uint32_t bh4[4], bl4[4];
            LDSM4(bh4, Bh + bbase + np * 16 * 80 + ks * 32);
            LDSM4(bl4, Bl + bbase + np * 16 * 80 + ks * 32);
            #pragma unroll
            for (int mt = 0; mt < 4; mt++) {
                mma_f16(acc[mt][2*np],   a[mt], bh4[0], bh4[1]);
                mma_f16(acc[mt][2*np],   a[mt], bl4[0], bl4[1]);
                mma_f16(acc[mt][2*np+1], a[mt], bh4[2], bh4[3]);
                mma_f16(acc[mt][2*np+1], a[mt], bl4[2], bl4[3]);
            }
        }
    }
}

__device__ __forceinline__ void chunk1(uint32_t A, uint32_t Bh,
                                       int arow, int bcol, int lane,
                                       float acc[4][4][4]) {
    const int hb = (lane >> 3) & 3;
    const uint32_t abase = (uint32_t)((arow + (lane & 15)) * 80 + (lane >> 4) * 16);
    const uint32_t bbase = (uint32_t)((bcol + (hb >> 1) * 8 + (lane & 7)) * 80 + (hb & 1) * 16);
    #pragma unroll
    for (int ks = 0; ks < 2; ks++) {
        uint32_t a[4][4];
        #pragma unroll
        for (int mt = 0; mt < 4; mt++)
            LDSM4(a[mt], A + abase + mt * 16 * 80 + ks * 32);
        #pragma unroll
        for (int np = 0; np < 2; np++) {
            uint32_t bh4[4];
            LDSM4(bh4, Bh + bbase + np * 16 * 80 + ks * 32);
            #pragma unroll
            for (int mt = 0; mt < 4; mt++) {
                mma_f16(acc[mt][2*np],   a[mt], bh4[0], bh4[1]);
                mma_f16(acc[mt][2*np+1], a[mt], bh4[2], bh4[3]);
            }
        }
    }
}

// ---------------------------------------------------------------------------
// 128x128 GEMM, K=1024, THREE-stage cp.async pipeline (load gets 2 compute
// chunks of slack), single sync per chunk. TERMS=2: B hi/lo; TERMS=1: B hi.
// ---------------------------------------------------------------------------
template<int TERMS, typename EPI>
__device__ __forceinline__ void gemm128(
    const __half* A, const __half* Bh, const __half* Bl, int tid, EPI epi)
{
    constexpr uint32_t STG = (TERMS == 2) ? 30720 : 20480;
    extern __shared__ char sm[];
    const uint32_t sb = smem_u32(sm);
    const int lane = tid & 31, wid = tid >> 5;
    const int wm = wid & 1, wn = wid >> 1;   // 2 x 4 warp grid

    auto issue = [&](int c, int st) {
        uint32_t base = sb + st * STG;
        #pragma unroll 2
        for (int idx = tid; idx < 512; idx += 256) {
            int r = idx >> 2, f = idx & 3;
            uint32_t so = (uint32_t)(r * 80 + f * 16);
            size_t go = (size_t)r * 1024 + c * 32 + f * 8;
            cpa16(base + so,         A + go);
            cpa16(base + 10240 + so, Bh + go);
            if (TERMS == 2) cpa16(base + 20480 + so, Bl + go);
        }
        CP_COMMIT();
    };

    float acc[4][4][4];
    #pragma unroll
    for (int i = 0; i < 4; i++)
        #pragma unroll
        for (int j = 0; j < 4; j++)
            #pragma unroll
            for (int l = 0; l < 4; l++) acc[i][j][l] = 0.f;

    issue(0, 0);
    issue(1, 1);
    for (int c = 0; c < 32; c++) {
        if (c == 31) { CP_WAIT(0); } else { CP_WAIT(1); }
        __syncthreads();
        if (c + 2 < 32) issue(c + 2, (c + 2) % 3);
        uint32_t s = sb + (c % 3) * STG;
        if (TERMS == 2) chunk2(s, s + 10240, s + 20480, wm * 64, wn * 32, lane, acc);
        else            chunk1(s, s + 10240,            wm * 64, wn * 32, lane, acc);
    }
    epi(acc, wm, wn, lane);
}

#define GEMM_SMEM  (3*30720)   // proj (2-term stages)
#define GEMM1_SMEM (3*20480)   // outproj (1-term stages)

// ---------------------------------------------------------------------------
// Kernel: QKV projections. grid (8, 64, 3). q,k: 2-term weights; v: single.
// ---------------------------------------------------------------------------
__global__ void __launch_bounds__(256, 2) proj_kernel(
    const float* __restrict__ qb, const float* __restrict__ kb, const float* __restrict__ vb)
{
    const int z = blockIdx.z;
    const int tid = threadIdx.x;
    const int m0 = blockIdx.y * 128, n0 = blockIdx.x * 128;
    const __half* A  = g_x  + (size_t)z * IN_ELEMS + (size_t)m0 * 1024;
    const __half* Bh = g_wh + (size_t)z * W_ELEMS + (size_t)n0 * 1024;
    const __half* Bl = g_wl + (size_t)z * W_ELEMS + (size_t)n0 * 1024;
    const float* bias = (z == 0) ? qb : ((z == 1) ? kb : vb);

    auto epi = [&](float acc[4][4][4], int wm, int wn, int lane) {
        const int g = lane >> 2, t = lane & 3;
        #pragma unroll
        for (int mt = 0; mt < 4; mt++) {
            int m = m0 + wm * 64 + mt * 16 + g;
            int bb = m >> 10, s = m & 1023;
            #pragma unroll
            for (int nt = 0; nt < 4; nt++) {
                int n = n0 + wn * 32 + nt * 8 + t * 2;
                int h = n >> 6, d = n & 63;
                float2 bv = *(const float2*)(bias + n);
                float c0 = acc[mt][nt][0] + bv.x, c1 = acc[mt][nt][1] + bv.y;
                float c2 = acc[mt][nt][2] + bv.x, c3 = acc[mt][nt][3] + bv.y;
                if (z < 2) {
                    __half* dst = (z == 0) ? g_q : g_k;
                    size_t a0 = (((size_t)bb * Hn + h) * Sn + s) * Dn + d;
                    *(uint32_t*)(dst + a0)          = packh2(c0, c1);
                    *(uint32_t*)(dst + a0 + 8 * Dn) = packh2(c2, c3);
                } else {
                    // V transposed (b,h,d,s), single fp16
                    size_t a0 = (((size_t)bb * Hn + h) * Dn + d) * Sn + s;
                    g_vt[a0]          = __float2half_rn(c0);
                    g_vt[a0 + Sn]     = __float2half_rn(c1);
                    g_vt[a0 + 8]      = __float2half_rn(c2);
                    g_vt[a0 + Sn + 8] = __float2half_rn(c3);
                }
            }
        }
    };

    if (z < 2) gemm128<2>(A, Bh, Bl, tid, epi);
    else       gemm128<1>(A, Bh, Bl, tid, epi);
}

// ---------------------------------------------------------------------------
// Pass 1: softmax row sums (single fp16 scores — identical math to pass 2).
// grid (8, 128)
// ---------------------------------------------------------------------------
#define SQ 0
#define SKH(st) (18432 + (st)*9216)
#define SSUM 36864
#define SUM_SMEM 37376

__global__ void __launch_bounds__(256, 2) sum_kernel()
{
    extern __shared__ char sm[];
    const uint32_t sb = smem_u32(sm);
    float* sums = (float*)(sm + SSUM);

    const int tid = threadIdx.x, lane = tid & 31, w = tid >> 5;
    const int g = lane >> 2, t = lane & 3;
    const int wr = w * 16;
    const int hb = (lane >> 3) & 3;
    const int m0 = blockIdx.x * 128;
    const int bh = blockIdx.y;

    const __half* Qg  = g_q + ((size_t)bh * Sn + m0) * Dn;
    const __half* Khg = g_k + (size_t)bh * Sn * Dn;

    auto issueK = [&](int c, int st) {
        uint32_t base = sb + SKH(st);
        #pragma unroll
        for (int j = 0; j < 2; j++) {
            int idx = tid + j * 256;
            int r = idx >> 3, f = idx & 7;
            cpa16(base + r * 144 + f * 16, Khg + (size_t)(c * 64 + r) * Dn + f * 8);
        }
    };

    #pragma unroll
    for (int j = 0; j < 4; j++) {
        int idx = tid + j * 256;
        int r = idx >> 3, f = idx & 7;
        cpa16(sb + SQ + r * 144 + f * 16, Qg + (size_t)r * Dn + f * 8);
    }
    issueK(0, 0);
    CP_COMMIT();

    float rs0 = 0.f, rs1 = 0.f;
    for (int c = 0; c < 16; c++) {
        CP_WAIT(0);
        __syncthreads();
        if (c + 1 < 16) { issueK(c + 1, (c + 1) & 1); CP_COMMIT(); }
        const uint32_t stg = sb + SKH(c & 1);

        float sa[8][4];
        #pragma unroll
        for (int i = 0; i < 8; i++)
            #pragma unroll
            for (int l = 0; l < 4; l++) sa[i][l] = 0.f;
        #pragma unroll
        for (int ks = 0; ks < 4; ks++) {
            uint32_t qa[4];
            LDSM4(qa, sb + SQ + (wr + (lane & 15)) * 144 + (lane >> 4) * 16 + ks * 32);
            #pragma unroll
            for (int np = 0; np < 4; np++) {
                uint32_t bo = (uint32_t)((np * 16 + (hb >> 1) * 8 + (lane & 7)) * 144
                                         + (hb & 1) * 16 + ks * 32);
                uint32_t kh4[4];
                LDSM4(kh4, stg + bo);
                mma_f16(sa[2*np],   qa, kh4[0], kh4[1]);
                mma_f16(sa[2*np+1], qa, kh4[2], kh4[3]);
            }
        }
        #pragma unroll
        for (int j = 0; j < 8; j++) {
            rs0 += __expf(sa[j][0] * 0.125f) + __expf(sa[j][1] * 0.125f);
            rs1 += __expf(sa[j][2] * 0.125f) + __expf(sa[j][3] * 0.125f);
        }
    }

    rs0 += __shfl_xor_sync(0xffffffffu, rs0, 1);
    rs0 += __shfl_xor_sync(0xffffffffu, rs0, 2);
    rs1 += __shfl_xor_sync(0xffffffffu, rs1, 1);
    rs1 += __shfl_xor_sync(0xffffffffu, rs1, 2);
    if (t == 0) { sums[wr + g] = rs0; sums[wr + g + 8] = rs1; }
    __syncthreads();
    if (tid < 128)
        g_inv[((size_t)bh << 10) + m0 + tid] = 1.0f / sums[tid];
}

// ---------------------------------------------------------------------------
// Pass 2: fused attention (unchanged from R12: K,V single fp16).
// ---------------------------------------------------------------------------
#define FQ 0
#define FST(st) (18432 + (st)*18432)
#define FUSED_SMEM 55296

__global__ void __launch_bounds__(256, 2) fused_attn_kernel(float* __restrict__ attn)
{
    extern __shared__ char sm[];
    const uint32_t sb = smem_u32(sm);

    const int tid = threadIdx.x, lane = tid & 31, w = tid >> 5;
    const int g = lane >> 2, t = lane & 3;
    const int wm = w & 3, wn = w >> 2;      // 4 m-warps x 2 n-warps
    const int wr = wm * 32;
    const int hb = (lane >> 3) & 3;
    const int m0 = blockIdx.x * 128;
    const int bh = blockIdx.y;

    const __half* Qg  = g_q  + ((size_t)bh * Sn + m0) * Dn;
    const __half* Khg = g_k  + (size_t)bh * Sn * Dn;
    const __half* Vhg = g_vt + (size_t)bh * Dn * Sn;
    float* attnB = attn + ((size_t)bh * Sn + m0) * Sn;

    const float* invb = g_inv + ((size_t)bh << 10) + m0 + wr;
    float ivA[2], ivB[2];
    ivA[0] = invb[g];       ivB[0] = invb[g + 8];
    ivA[1] = invb[16 + g];  ivB[1] = invb[16 + 8 + g];

    auto issueKV = [&](int c, int st) {
        uint32_t base = sb + FST(st);
        #pragma unroll
        for (int j = 0; j < 2; j++) {
            int idx = tid + j * 256;
            int r = idx >> 3, f = idx & 7;
            cpa16(base + r * 144 + f * 16, Khg + (size_t)(c * 64 + r) * Dn + f * 8);
        }
        #pragma unroll
        for (int j = 0; j < 2; j++) {
            int idx = tid + j * 256;
            int d = idx >> 3, f = idx & 7;
            cpa16(base + 9216 + d * 144 + f * 16, Vhg + (size_t)d * Sn + c * 64 + f * 8);
        }
    };

    #pragma unroll
    for (int j = 0; j < 4; j++) {
        int idx = tid + j * 256;
        int r = idx >> 3, f = idx & 7;
        cpa16(sb + FQ + r * 144 + f * 16, Qg + (size_t)r * Dn + f * 8);
    }
    issueKV(0, 0);
    CP_COMMIT();

    float O[2][8][4];
    #pragma unroll
    for (int i = 0; i < 2; i++)
        #pragma unroll
        for (int j = 0; j < 8; j++)
            #pragma unroll
            for (int l = 0; l < 4; l++) O[i][j][l] = 0.f;

    for (int c = 0; c < 16; c++) {
        CP_WAIT(0);
        __syncthreads();
        if (c + 1 < 16) { issueKV(c + 1, (c + 1) & 1); CP_COMMIT(); }
        const uint32_t stg = sb + FST(c & 1);

        #pragma unroll
        for (int kg = 0; kg < 2; kg++) {
            const int kloc = wn * 32 + kg * 16;

            float sa[2][2][4];
            #pragma unroll
            for (int i = 0; i < 2; i++)
                #pragma unroll
                for (int j = 0; j < 2; j++)
                    #pragma unroll
                    for (int l = 0; l < 4; l++) sa[i][j][l] = 0.f;
            #pragma unroll
            for (int ks = 0; ks < 4; ks++) {
                uint32_t qa0[4], qa1[4];
                uint32_t qo = sb + FQ + (wr + (lane & 15)) * 144 + (lane >> 4) * 16 + ks * 32;
                LDSM4(qa0, qo);
                LDSM4(qa1, qo + 16 * 144);
                uint32_t bo = (uint32_t)((kloc + (hb >> 1) * 8 + (lane & 7)) * 144
                                         + (hb & 1) * 16 + ks * 32);
                uint32_t kh4[4];
                LDSM4(kh4, stg + bo);
                mma_f16(sa[0][0], qa0, kh4[0], kh4[1]);
                mma_f16(sa[1][0], qa1, kh4[0], kh4[1]);
                mma_f16(sa[0][1], qa0, kh4[2], kh4[3]);
                mma_f16(sa[1][1], qa1, kh4[2], kh4[3]);
            }
            const int cb = c * 64 + kloc;
            #pragma unroll
            for (int mt = 0; mt < 2; mt++) {
                float* r0 = attnB + (size_t)(wr + mt * 16 + g) * Sn + cb;
                float* r1 = attnB + (size_t)(wr + mt * 16 + g + 8) * Sn + cb;
                #pragma unroll
                for (int nt = 0; nt < 2; nt++) {
                    float e0 = __expf(sa[mt][nt][0] * 0.125f) * ivA[mt];
                    float e1 = __expf(sa[mt][nt][1] * 0.125f) * ivA[mt];
                    float e2 = __expf(sa[mt][nt][2] * 0.125f) * ivB[mt];
                    float e3 = __expf(sa[mt][nt][3] * 0.125f) * ivB[mt];
                    *(float2*)(r0 + nt * 8 + t * 2) = make_float2(e0, e1);
                    *(float2*)(r1 + nt * 8 + t * 2) = make_float2(e2, e3);
                    sa[mt][nt][0] = e0; sa[mt][nt][1] = e1;
                    sa[mt][nt][2] = e2; sa[mt][nt][3] = e3;
                }
            }
            uint32_t PA[2][4];
            #pragma unroll
            for (int mt = 0; mt < 2; mt++) {
                PA[mt][0] = packh2(sa[mt][0][0], sa[mt][0][1]);
                PA[mt][1] = packh2(sa[mt][0][2], sa[mt][0][3]);
                PA[mt][2] = packh2(sa[mt][1][0], sa[mt][1][1]);
                PA[mt][3] = packh2(sa[mt][1][2], sa[mt][1][3]);
            }
            #pragma unroll
            for (int npd = 0; npd < 4; npd++) {
                uint32_t bo = (uint32_t)((npd * 16 + (hb >> 1) * 8 + (lane & 7)) * 144
                                         + (hb & 1) * 16 + kloc * 2);
                uint32_t vh4[4];
                LDSM4(vh4, stg + 9216 + bo);
                mma_f16(O[0][2*npd],   PA[0], vh4[0], vh4[1]);
                mma_f16(O[1][2*npd],   PA[1], vh4[0], vh4[1]);
                mma_f16(O[0][2*npd+1], PA[0], vh4[2], vh4[3]);
                mma_f16(O[1][2*npd+1], PA[1], vh4[2], vh4[3]);
            }
        }
    }

    // ---- merge key-half partials via smem, write ctx ----
    __syncthreads();
    float* red = (float*)(sm + FST(0));     // 128 x 64 = 32 KB
    if (wn == 1) {
        #pragma unroll
        for (int mt = 0; mt < 2; mt++)
            #pragma unroll
            for (int nt = 0; nt < 8; nt++) {
                int b0 = (wr + mt * 16 + g) * 64 + nt * 8 + t * 2;
                int b1 = (wr + mt * 16 + g + 8) * 64 + nt * 8 + t * 2;
                *(float2*)(red + b0) = make_float2(O[mt][nt][0], O[mt][nt][1]);
                *(float2*)(red + b1) = make_float2(O[mt][nt][2], O[mt][nt][3]);
            }
    }
    __syncthreads();
    if (wn == 0) {
        const int bb = bh >> 4, h = bh & 15;
        #pragma unroll
        for (int mt = 0; mt < 2; mt++) {
            int m = m0 + wr + mt * 16 + g;
            __half* c0 = g_ctx + ((size_t)(bb * Sn + m)) * En + h * Dn;
            __half* c1 = g_ctx + ((size_t)(bb * Sn + m + 8)) * En + h * Dn;
            #pragma unroll
            for (int nt = 0; nt < 8; nt++) {
                int b0 = (wr + mt * 16 + g) * 64 + nt * 8 + t * 2;
                int b1 = (wr + mt * 16 + g + 8) * 64 + nt * 8 + t * 2;
                float2 p0 = *(float2*)(red + b0);
                float2 p1 = *(float2*)(red + b1);
                int d = nt * 8 + t * 2;
                *(uint32_t*)(c0 + d) = packh2(O[mt][nt][0] + p0.x, O[mt][nt][1] + p0.y);
                *(uint32_t*)(c1 + d) = packh2(O[mt][nt][2] + p1.x, O[mt][nt][3] + p1.y);
            }
        }
    }
}

// ---------------------------------------------------------------------------
// Kernel: output projection (single-term weights). grid (8, 64)
// ---------------------------------------------------------------------------
__global__ void __launch_bounds__(256, 2) outproj_kernel(
    const float* __restrict__ ob, float* __restrict__ Out)
{
    const int tid = threadIdx.x;
    const int m0 = blockIdx.y * 128, n0 = blockIdx.x * 128;
    const __half* A  = g_ctx + (size_t)m0 * 1024;
    const __half* Bh = g_wh + (size_t)3 * W_ELEMS + (size_t)n0 * 1024;

    gemm128<1>(A, Bh, nullptr, tid,
        [&](float acc[4][4][4], int wm, int wn, int lane) {
            const int g = lane >> 2, t = lane & 3;
            #pragma unroll
            for (int mt = 0; mt < 4; mt++) {
                int m = m0 + wm * 64 + mt * 16 + g;
                float* orow = Out + (size_t)m * En;
                #pragma unroll
                for (int nt = 0; nt < 4; nt++) {
                    int n = n0 + wn * 32 + nt * 8 + t * 2;
                    float2 bv = *(const float2*)(ob + n);
                    *(float2*)(orow + n) =
                        make_float2(acc[mt][nt][0] + bv.x, acc[mt][nt][1] + bv.y);
                    *(float2*)(orow + 8 * En + n) =
                        make_float2(acc[mt][nt][2] + bv.x, acc[mt][nt][3] + bv.y);
                }
            }
        });
}

// ---------------------------------------------------------------------------
extern "C" void kernel_launch(void* const* d_in, const int* in_sizes, int n_in,
                              void* d_out, int out_size)
{
    const float* q_in  = (const float*)d_in[0];
    const float* k_in  = (const float*)d_in[1];
    const float* v_in  = (const float*)d_in[2];
    const float* q_w   = (const float*)d_in[3];
    const float* q_b   = (const float*)d_in[4];
    const float* k_w   = (const float*)d_in[5];
    const float* k_b   = (const float*)d_in[6];
    const float* v_w   = (const float*)d_in[7];
    const float* v_b   = (const float*)d_in[8];
    const float* out_w = (const float*)d_in[9];
    const float* out_b = (const float*)d_in[10];

    float* out  = (float*)d_out;
    float* attn = out;                  // (B,H,S,S)
    float* outp = out + ATTN_ELEMS;     // (B,S,E)

    cudaFuncSetAttribute(proj_kernel,       cudaFuncAttributeMaxDynamicSharedMemorySize, GEMM_SMEM);
    cudaFuncSetAttribute(sum_kernel,        cudaFuncAttributeMaxDynamicSharedMemorySize, SUM_SMEM);
    cudaFuncSetAttribute(fused_attn_kernel, cudaFuncAttributeMaxDynamicSharedMemorySize, FUSED_SMEM);
    cudaFuncSetAttribute(outproj_kernel,    cudaFuncAttributeMaxDynamicSharedMemorySize, GEMM1_SMEM);

    split_kernel<<<dim3(8192, 7), 256>>>(q_in, k_in, v_in, q_w, k_w, v_w, out_w);
    proj_kernel<<<dim3(8, 64, 3), 256, GEMM_SMEM>>>(q_b, k_b, v_b);
    sum_kernel<<<dim3(8, 128), 256, SUM_SMEM>>>();
    fused_attn_kernel<<<dim3(8, 128), 256, FUSED_SMEM>>>(attn);
    outproj_kernel<<<dim3(8, 64), 256, GEMM1_SMEM>>>(out_b, outp);
}

// round 14
// speedup vs baseline: 1.5130x; 1.1413x over previous
#include <cuda_runtime.h>
#include <cuda_fp16.h>
#include <cstdint>

#define Bn 8
#define Sn 1024
#define En 1024
#define Hn 16
#define Dn 64
#define ATTN_ELEMS ((size_t)Bn*Hn*Sn*Sn)
#define IN_ELEMS (Bn*Sn*En)     // 8388608
#define W_ELEMS  (En*En)        // 1048576

// fp16 operand storage (allocation-free rule: __device__ globals)
__device__ __half g_x[3*IN_ELEMS];                     // inputs q,k,v (single)
__device__ __half g_wh[4*W_ELEMS];                     // weights single fp16
__device__ __half g_q[IN_ELEMS];                       // (b,h,s,d) single
__device__ __half g_k[IN_ELEMS];                       // (b,h,s,d) single
__device__ __half g_vt[IN_ELEMS];                      // (b,h,d,s) single, transposed
__device__ __half g_ctx[IN_ELEMS];                     // (b,s,e) single
__device__ float g_inv[Bn*Hn*Sn];                      // softmax 1/rowsum

// ---------------- PTX primitives ----------------
__device__ __forceinline__ uint32_t smem_u32(const void* p) {
    uint32_t a;
    asm("{ .reg .u64 t; cvta.to.shared.u64 t, %1; cvt.u32.u64 %0, t; }" : "=r"(a) : "l"(p));
    return a;
}
__device__ __forceinline__ void cpa16(uint32_t sdst, const void* gsrc) {
    asm volatile("cp.async.cg.shared.global [%0], [%1], 16;" :: "r"(sdst), "l"(gsrc));
}
#define CP_COMMIT() asm volatile("cp.async.commit_group;" ::: "memory")
#define CP_WAIT(N)  asm volatile("cp.async.wait_group %0;" :: "n"(N) : "memory")

#define LDSM4(R, A) asm volatile("ldmatrix.sync.aligned.m8n8.x4.shared.b16 {%0,%1,%2,%3}, [%4];" \
    : "=r"((R)[0]), "=r"((R)[1]), "=r"((R)[2]), "=r"((R)[3]) : "r"(A))

__device__ __forceinline__ void mma_f16(float c[4], const uint32_t a[4],
                                        uint32_t b0, uint32_t b1) {
    asm volatile(
        "mma.sync.aligned.m16n8k16.row.col.f32.f16.f16.f32 "
        "{%0,%1,%2,%3}, {%4,%5,%6,%7}, {%8,%9}, {%0,%1,%2,%3};"
        : "+f"(c[0]), "+f"(c[1]), "+f"(c[2]), "+f"(c[3])
        : "r"(a[0]), "r"(a[1]), "r"(a[2]), "r"(a[3]), "r"(b0), "r"(b1));
}

__device__ __forceinline__ uint32_t packh2(float a, float b) {
    __half2 h = __floats2half2_rn(a, b);
    return *(uint32_t*)&h;
}

// ---------------------------------------------------------------------------
// split_kernel: everything -> single fp16. grid (8192, 7)
// ---------------------------------------------------------------------------
__global__ void __launch_bounds__(256) split_kernel(
    const float* __restrict__ xq, const float* __restrict__ xk, const float* __restrict__ xv,
    const float* __restrict__ wq, const float* __restrict__ wk,
    const float* __restrict__ wv, const float* __restrict__ wo)
{
    const int z = blockIdx.y;
    int i = blockIdx.x * 256 + threadIdx.x;
    const float* src;
    __half* dst;
    int n4;
    if (z < 3) {
        src = (z == 0) ? xq : ((z == 1) ? xk : xv);
        dst = g_x + (size_t)z * IN_ELEMS;
        n4 = IN_ELEMS / 4;
    } else {
        src = (z == 3) ? wq : ((z == 4) ? wk : ((z == 5) ? wv : wo));
        dst = g_wh + (size_t)(z - 3) * W_ELEMS;
        n4 = W_ELEMS / 4;
    }
    if (i >= n4) return;
    float4 v = ((const float4*)src)[i];
    uint2 o;
    o.x = packh2(v.x, v.y);
    o.y = packh2(v.z, v.w);
    ((uint2*)dst)[i] = o;
}

// ---------------------------------------------------------------------------
// Warp MMA on a K=32 chunk (both operands single fp16), stride 80.
// Warp tile 64 rows x 32 cols.
// ---------------------------------------------------------------------------
__device__ __forceinline__ void chunk1(uint32_t A, uint32_t Bh,
                                       int arow, int bcol, int lane,
                                       float acc[4][4][4]) {
    const int hb = (lane >> 3) & 3;
    const uint32_t abase = (uint32_t)((arow + (lane & 15)) * 80 + (lane >> 4) * 16);
    const uint32_t bbase = (uint32_t)((bcol + (hb >> 1) * 8 + (lane & 7)) * 80 + (hb & 1) * 16);
    #pragma unroll
    for (int ks = 0; ks < 2; ks++) {
        uint32_t a[4][4];
        #pragma unroll
        for (int mt = 0; mt < 4; mt++)
            LDSM4(a[mt], A + abase + mt * 16 * 80 + ks * 32);
        #pragma unroll
        for (int np = 0; np < 2; np++) {
            uint32_t bh4[4];
            LDSM4(bh4, Bh + bbase + np * 16 * 80 + ks * 32);
            #pragma unroll
            for (int mt = 0; mt < 4; mt++) {
                mma_f16(acc[mt][2*np],   a[mt], bh4[0], bh4[1]);
                mma_f16(acc[mt][2*np+1], a[mt], bh4[2], bh4[3]);
            }
        }
    }
}

// ---------------------------------------------------------------------------
// 128x128 GEMM, K=1024, 3-stage cp.async pipeline, single sync per chunk.
// ---------------------------------------------------------------------------
#define GSTG 20480
#define GEMM_SMEM (3*GSTG)

template<typename EPI>
__device__ __forceinline__ void gemm128(
    const __half* A, const __half* Bh, int tid, EPI epi)
{
    extern __shared__ char sm[];
    const uint32_t sb = smem_u32(sm);
    const int lane = tid & 31, wid = tid >> 5;
    const int wm = wid & 1, wn = wid >> 1;   // 2 x 4 warp grid

    auto issue = [&](int c, int st) {
        uint32_t base = sb + st * GSTG;
        #pragma unroll 2
        for (int idx = tid; idx < 512; idx += 256) {
            int r = idx >> 2, f = idx & 3;
            uint32_t so = (uint32_t)(r * 80 + f * 16);
            size_t go = (size_t)r * 1024 + c * 32 + f * 8;
            cpa16(base + so,         A + go);
            cpa16(base + 10240 + so, Bh + go);
        }
        CP_COMMIT();
    };

    float acc[4][4][4];
    #pragma unroll
    for (int i = 0; i < 4; i++)
        #pragma unroll
        for (int j = 0; j < 4; j++)
            #pragma unroll
            for (int l = 0; l < 4; l++) acc[i][j][l] = 0.f;

    issue(0, 0);
    issue(1, 1);
    for (int c = 0; c < 32; c++) {
        if (c == 31) { CP_WAIT(0); } else { CP_WAIT(1); }
        __syncthreads();
        if (c + 2 < 32) issue(c + 2, (c + 2) % 3);
        uint32_t s = sb + (c % 3) * GSTG;
        chunk1(s, s + 10240, wm * 64, wn * 32, lane, acc);
    }
    epi(acc, wm, wn, lane);
}

// ---------------------------------------------------------------------------
// Kernel: QKV projections. grid (8, 64, 3). Single-fp16 weights throughout.
// ---------------------------------------------------------------------------
__global__ void __launch_bounds__(256, 2) proj_kernel(
    const float* __restrict__ qb, const float* __restrict__ kb, const float* __restrict__ vb)
{
    const int z = blockIdx.z;
    const int tid = threadIdx.x;
    const int m0 = blockIdx.y * 128, n0 = blockIdx.x * 128;
    const __half* A  = g_x  + (size_t)z * IN_ELEMS + (size_t)m0 * 1024;
    const __half* Bh = g_wh + (size_t)z * W_ELEMS + (size_t)n0 * 1024;
    const float* bias = (z == 0) ? qb : ((z == 1) ? kb : vb);

    gemm128(A, Bh, tid,
        [&](float acc[4][4][4], int wm, int wn, int lane) {
            const int g = lane >> 2, t = lane & 3;
            #pragma unroll
            for (int mt = 0; mt < 4; mt++) {
                int m = m0 + wm * 64 + mt * 16 + g;
                int bb = m >> 10, s = m & 1023;
                #pragma unroll
                for (int nt = 0; nt < 4; nt++) {
                    int n = n0 + wn * 32 + nt * 8 + t * 2;
                    int h = n >> 6, d = n & 63;
                    float2 bv = *(const float2*)(bias + n);
                    float c0 = acc[mt][nt][0] + bv.x, c1 = acc[mt][nt][1] + bv.y;
                    float c2 = acc[mt][nt][2] + bv.x, c3 = acc[mt][nt][3] + bv.y;
                    if (z < 2) {
                        __half* dst = (z == 0) ? g_q : g_k;
                        size_t a0 = (((size_t)bb * Hn + h) * Sn + s) * Dn + d;
                        *(uint32_t*)(dst + a0)          = packh2(c0, c1);
                        *(uint32_t*)(dst + a0 + 8 * Dn) = packh2(c2, c3);
                    } else {
                        // V transposed (b,h,d,s), single fp16
                        size_t a0 = (((size_t)bb * Hn + h) * Dn + d) * Sn + s;
                        g_vt[a0]          = __float2half_rn(c0);
                        g_vt[a0 + Sn]     = __float2half_rn(c1);
                        g_vt[a0 + 8]      = __float2half_rn(c2);
                        g_vt[a0 + Sn + 8] = __float2half_rn(c3);
                    }
                }
            }
        });
}

// ---------------------------------------------------------------------------
// Pass 1: softmax row sums (single fp16 scores — identical math to pass 2).
// grid (8, 128)
// ---------------------------------------------------------------------------
#define SQ 0
#define SKH(st) (18432 + (st)*9216)
#define SSUM 36864
#define SUM_SMEM 37376

__global__ void __launch_bounds__(256, 2) sum_kernel()
{
    extern __shared__ char sm[];
    const uint32_t sb = smem_u32(sm);
    float* sums = (float*)(sm + SSUM);

    const int tid = threadIdx.x, lane = tid & 31, w = tid >> 5;
    const int g = lane >> 2, t = lane & 3;
    const int wr = w * 16;
    const int hb = (lane >> 3) & 3;
    const int m0 = blockIdx.x * 128;
    const int bh = blockIdx.y;

    const __half* Qg  = g_q + ((size_t)bh * Sn + m0) * Dn;
    const __half* Khg = g_k + (size_t)bh * Sn * Dn;

    auto issueK = [&](int c, int st) {
        uint32_t base = sb + SKH(st);
        #pragma unroll
        for (int j = 0; j < 2; j++) {
            int idx = tid + j * 256;
            int r = idx >> 3, f = idx & 7;
            cpa16(base + r * 144 + f * 16, Khg + (size_t)(c * 64 + r) * Dn + f * 8);
        }
    };

    #pragma unroll
    for (int j = 0; j < 4; j++) {
        int idx = tid + j * 256;
        int r = idx >> 3, f = idx & 7;
        cpa16(sb + SQ + r * 144 + f * 16, Qg + (size_t)r * Dn + f * 8);
    }
    issueK(0, 0);
    CP_COMMIT();

    float rs0 = 0.f, rs1 = 0.f;
    for (int c = 0; c < 16; c++) {
        CP_WAIT(0);
        __syncthreads();
        if (c + 1 < 16) { issueK(c + 1, (c + 1) & 1); CP_COMMIT(); }
        const uint32_t stg = sb + SKH(c & 1);

        float sa[8][4];
        #pragma unroll
        for (int i = 0; i < 8; i++)
            #pragma unroll
            for (int l = 0; l < 4; l++) sa[i][l] = 0.f;
        #pragma unroll
        for (int ks = 0; ks < 4; ks++) {
            uint32_t qa[4];
            LDSM4(qa, sb + SQ + (wr + (lane & 15)) * 144 + (lane >> 4) * 16 + ks * 32);
            #pragma unroll
            for (int np = 0; np < 4; np++) {
                uint32_t bo = (uint32_t)((np * 16 + (hb >> 1) * 8 + (lane & 7)) * 144
                                         + (hb & 1) * 16 + ks * 32);
                uint32_t kh4[4];
                LDSM4(kh4, stg + bo);
                mma_f16(sa[2*np],   qa, kh4[0], kh4[1]);
                mma_f16(sa[2*np+1], qa, kh4[2], kh4[3]);
            }
        }
        #pragma unroll
        for (int j = 0; j < 8; j++) {
            rs0 += __expf(sa[j][0] * 0.125f) + __expf(sa[j][1] * 0.125f);
            rs1 += __expf(sa[j][2] * 0.125f) + __expf(sa[j][3] * 0.125f);
        }
    }

    rs0 += __shfl_xor_sync(0xffffffffu, rs0, 1);
    rs0 += __shfl_xor_sync(0xffffffffu, rs0, 2);
    rs1 += __shfl_xor_sync(0xffffffffu, rs1, 1);
    rs1 += __shfl_xor_sync(0xffffffffu, rs1, 2);
    if (t == 0) { sums[wr + g] = rs0; sums[wr + g + 8] = rs1; }
    __syncthreads();
    if (tid < 128)
        g_inv[((size_t)bh << 10) + m0 + tid] = 1.0f / sums[tid];
}

// ---------------------------------------------------------------------------
// Pass 2: fused attention (K,V single fp16). grid (8, 128)
// smem: Q@0 (18432) | stage st @ 18432+st*18432: KH+0 VH+9216. Total 55296.
// ---------------------------------------------------------------------------
#define FQ 0
#define FST(st) (18432 + (st)*18432)
#define FUSED_SMEM 55296

__global__ void __launch_bounds__(256, 2) fused_attn_kernel(float* __restrict__ attn)
{
    extern __shared__ char sm[];
    const uint32_t sb = smem_u32(sm);

    const int tid = threadIdx.x, lane = tid & 31, w = tid >> 5;
    const int g = lane >> 2, t = lane & 3;
    const int wm = w & 3, wn = w >> 2;      // 4 m-warps x 2 n-warps
    const int wr = wm * 32;
    const int hb = (lane >> 3) & 3;
    const int m0 = blockIdx.x * 128;
    const int bh = blockIdx.y;

    const __half* Qg  = g_q  + ((size_t)bh * Sn + m0) * Dn;
    const __half* Khg = g_k  + (size_t)bh * Sn * Dn;
    const __half* Vhg = g_vt + (size_t)bh * Dn * Sn;
    float* attnB = attn + ((size_t)bh * Sn + m0) * Sn;

    const float* invb = g_inv + ((size_t)bh << 10) + m0 + wr;
    float ivA[2], ivB[2];
    ivA[0] = invb[g];       ivB[0] = invb[g + 8];
    ivA[1] = invb[16 + g];  ivB[1] = invb[16 + 8 + g];

    auto issueKV = [&](int c, int st) {
        uint32_t base = sb + FST(st);
        #pragma unroll
        for (int j = 0; j < 2; j++) {
            int idx = tid + j * 256;
            int r = idx >> 3, f = idx & 7;
            cpa16(base + r * 144 + f * 16, Khg + (size_t)(c * 64 + r) * Dn + f * 8);
        }
        #pragma unroll
        for (int j = 0; j < 2; j++) {
            int idx = tid + j * 256;
            int d = idx >> 3, f = idx & 7;
            cpa16(base + 9216 + d * 144 + f * 16, Vhg + (size_t)d * Sn + c * 64 + f * 8);
        }
    };

    #pragma unroll
    for (int j = 0; j < 4; j++) {
        int idx = tid + j * 256;
        int r = idx >> 3, f = idx & 7;
        cpa16(sb + FQ + r * 144 + f * 16, Qg + (size_t)r * Dn + f * 8);
    }
    issueKV(0, 0);
    CP_COMMIT();

    float O[2][8][4];
    #pragma unroll
    for (int i = 0; i < 2; i++)
        #pragma unroll
        for (int j = 0; j < 8; j++)
            #pragma unroll
            for (int l = 0; l < 4; l++) O[i][j][l] = 0.f;

    for (int c = 0; c < 16; c++) {
        CP_WAIT(0);
        __syncthreads();
        if (c + 1 < 16) { issueKV(c + 1, (c + 1) & 1); CP_COMMIT(); }
        const uint32_t stg = sb + FST(c & 1);

        #pragma unroll
        for (int kg = 0; kg < 2; kg++) {
            const int kloc = wn * 32 + kg * 16;

            float sa[2][2][4];
            #pragma unroll
            for (int i = 0; i < 2; i++)
                #pragma unroll
                for (int j = 0; j < 2; j++)
                    #pragma unroll
                    for (int l = 0; l < 4; l++) sa[i][j][l] = 0.f;
            #pragma unroll
            for (int ks = 0; ks < 4; ks++) {
                uint32_t qa0[4], qa1[4];
                uint32_t qo = sb + FQ + (wr + (lane & 15)) * 144 + (lane >> 4) * 16 + ks * 32;
                LDSM4(qa0, qo);
                LDSM4(qa1, qo + 16 * 144);
                uint32_t bo = (uint32_t)((kloc + (hb >> 1) * 8 + (lane & 7)) * 144
                                         + (hb & 1) * 16 + ks * 32);
                uint32_t kh4[4];
                LDSM4(kh4, stg + bo);
                mma_f16(sa[0][0], qa0, kh4[0], kh4[1]);
                mma_f16(sa[1][0], qa1, kh4[0], kh4[1]);
                mma_f16(sa[0][1], qa0, kh4[2], kh4[3]);
                mma_f16(sa[1][1], qa1, kh4[2], kh4[3]);
            }
            const int cb = c * 64 + kloc;
            #pragma unroll
            for (int mt = 0; mt < 2; mt++) {
                float* r0 = attnB + (size_t)(wr + mt * 16 + g) * Sn + cb;
                float* r1 = attnB + (size_t)(wr + mt * 16 + g + 8) * Sn + cb;
                #pragma unroll
                for (int nt = 0; nt < 2; nt++) {
                    float e0 = __expf(sa[mt][nt][0] * 0.125f) * ivA[mt];
                    float e1 = __expf(sa[mt][nt][1] * 0.125f) * ivA[mt];
                    float e2 = __expf(sa[mt][nt][2] * 0.125f) * ivB[mt];
                    float e3 = __expf(sa[mt][nt][3] * 0.125f) * ivB[mt];
                    *(float2*)(r0 + nt * 8 + t * 2) = make_float2(e0, e1);
                    *(float2*)(r1 + nt * 8 + t * 2) = make_float2(e2, e3);
                    sa[mt][nt][0] = e0; sa[mt][nt][1] = e1;
                    sa[mt][nt][2] = e2; sa[mt][nt][3] = e3;
                }
            }
            uint32_t PA[2][4];
            #pragma unroll
            for (int mt = 0; mt < 2; mt++) {
                PA[mt][0] = packh2(sa[mt][0][0], sa[mt][0][1]);
                PA[mt][1] = packh2(sa[mt][0][2], sa[mt][0][3]);
                PA[mt][2] = packh2(sa[mt][1][0], sa[mt][1][1]);
                PA[mt][3] = packh2(sa[mt][1][2], sa[mt][1][3]);
            }
            #pragma unroll
            for (int npd = 0; npd < 4; npd++) {
                uint32_t bo = (uint32_t)((npd * 16 + (hb >> 1) * 8 + (lane & 7)) * 144
                                         + (hb & 1) * 16 + kloc * 2);
                uint32_t vh4[4];
                LDSM4(vh4, stg + 9216 + bo);
                mma_f16(O[0][2*npd],   PA[0], vh4[0], vh4[1]);
                mma_f16(O[1][2*npd],   PA[1], vh4[0], vh4[1]);
                mma_f16(O[0][2*npd+1], PA[0], vh4[2], vh4[3]);
                mma_f16(O[1][2*npd+1], PA[1], vh4[2], vh4[3]);
            }
        }
    }

    // ---- merge key-half partials via smem, write ctx ----
    __syncthreads();
    float* red = (float*)(sm + FST(0));     // 128 x 64 = 32 KB
    if (wn == 1) {
        #pragma unroll
        for (int mt = 0; mt < 2; mt++)
            #pragma unroll
            for (int nt = 0; nt < 8; nt++) {
                int b0 = (wr + mt * 16 + g) * 64 + nt * 8 + t * 2;
                int b1 = (wr + mt * 16 + g + 8) * 64 + nt * 8 + t * 2;
                *(float2*)(red + b0) = make_float2(O[mt][nt][0], O[mt][nt][1]);
                *(float2*)(red + b1) = make_float2(O[mt][nt][2], O[mt][nt][3]);
            }
    }
    __syncthreads();
    if (wn == 0) {
        const int bb = bh >> 4, h = bh & 15;
        #pragma unroll
        for (int mt = 0; mt < 2; mt++) {
            int m = m0 + wr + mt * 16 + g;
            __half* c0 = g_ctx + ((size_t)(bb * Sn + m)) * En + h * Dn;
            __half* c1 = g_ctx + ((size_t)(bb * Sn + m + 8)) * En + h * Dn;
            #pragma unroll
            for (int nt = 0; nt < 8; nt++) {
                int b0 = (wr + mt * 16 + g) * 64 + nt * 8 + t * 2;
                int b1 = (wr + mt * 16 + g + 8) * 64 + nt * 8 + t * 2;
                float2 p0 = *(float2*)(red + b0);
                float2 p1 = *(float2*)(red + b1);
                int d = nt * 8 + t * 2;
                *(uint32_t*)(c0 + d) = packh2(O[mt][nt][0] + p0.x, O[mt][nt][1] + p0.y);
                *(uint32_t*)(c1 + d) = packh2(O[mt][nt][2] + p1.x, O[mt][nt][3] + p1.y);
            }
        }
    }
}

// ---------------------------------------------------------------------------
// Kernel: output projection (single-term weights). grid (8, 64)
// ---------------------------------------------------------------------------
__global__ void __launch_bounds__(256, 2) outproj_kernel(
    const float* __restrict__ ob, float* __restrict__ Out)
{
    const int tid = threadIdx.x;
    const int m0 = blockIdx.y * 128, n0 = blockIdx.x * 128;
    const __half* A  = g_ctx + (size_t)m0 * 1024;
    const __half* Bh = g_wh + (size_t)3 * W_ELEMS + (size_t)n0 * 1024;

    gemm128(A, Bh, tid,
        [&](float acc[4][4][4], int wm, int wn, int lane) {
            const int g = lane >> 2, t = lane & 3;
            #pragma unroll
            for (int mt = 0; mt < 4; mt++) {
                int m = m0 + wm * 64 + mt * 16 + g;
                float* orow = Out + (size_t)m * En;
                #pragma unroll
                for (int nt = 0; nt < 4; nt++) {
                    int n = n0 + wn * 32 + nt * 8 + t * 2;
                    float2 bv = *(const float2*)(ob + n);
                    *(float2*)(orow + n) =
                        make_float2(acc[mt][nt][0] + bv.x, acc[mt][nt][1] + bv.y);
                    *(float2*)(orow + 8 * En + n) =
                        make_float2(acc[mt][nt][2] + bv.x, acc[mt][nt][3] + bv.y);
                }
            }
        });
}

// ---------------------------------------------------------------------------
extern "C" void kernel_launch(void* const* d_in, const int* in_sizes, int n_in,
                              void* d_out, int out_size)
{
    const float* q_in  = (const float*)d_in[0];
    const float* k_in  = (const float*)d_in[1];
    const float* v_in  = (const float*)d_in[2];
    const float* q_w   = (const float*)d_in[3];
    const float* q_b   = (const float*)d_in[4];
    const float* k_w   = (const float*)d_in[5];
    const float* k_b   = (const float*)d_in[6];
    const float* v_w   = (const float*)d_in[7];
    const float* v_b   = (const float*)d_in[8];
    const float* out_w = (const float*)d_in[9];
    const float* out_b = (const float*)d_in[10];

    float* out  = (float*)d_out;
    float* attn = out;                  // (B,H,S,S)
    float* outp = out + ATTN_ELEMS;     // (B,S,E)

    cudaFuncSetAttribute(proj_kernel,       cudaFuncAttributeMaxDynamicSharedMemorySize, GEMM_SMEM);
    cudaFuncSetAttribute(sum_kernel,        cudaFuncAttributeMaxDynamicSharedMemorySize, SUM_SMEM);
    cudaFuncSetAttribute(fused_attn_kernel, cudaFuncAttributeMaxDynamicSharedMemorySize, FUSED_SMEM);
    cudaFuncSetAttribute(outproj_kernel,    cudaFuncAttributeMaxDynamicSharedMemorySize, GEMM_SMEM);

    split_kernel<<<dim3(8192, 7), 256>>>(q_in, k_in, v_in, q_w, k_w, v_w, out_w);
    proj_kernel<<<dim3(8, 64, 3), 256, GEMM_SMEM>>>(q_b, k_b, v_b);
    sum_kernel<<<dim3(8, 128), 256, SUM_SMEM>>>();
    fused_attn_kernel<<<dim3(8, 128), 256, FUSED_SMEM>>>(attn);
    outproj_kernel<<<dim3(8, 64), 256, GEMM_SMEM>>>(out_b, outp);
}